// round 10
// baseline (speedup 1.0000x reference)
#include <cuda_runtime.h>
#include <cuda_bf16.h>
#include <math.h>
#include <stdint.h>

// Problem constants
#define D_MODEL 512
#define H_ 8
#define HD_ 64
#define ETA_ 4
#define R_ 8
#define D_FFC 2048
#define T_ 128
#define B_ 32
#define NTOK (T_*B_)            // 4096
#define TOTAL_PROJ 2656
#define KQV_DIM 2560

typedef __nv_bfloat16 bf16;

#if defined(__CUDA_ARCH_FEAT_SM103_ALL) || defined(__CUDA_ARCH_FEAT_SM100_ALL)
#define HAS_TCGEN05 1
#else
#define HAS_TCGEN05 0
#endif

// ---------------------------------------------------------------------------
// Scratch
// ---------------------------------------------------------------------------
__device__ float g_allproj[NTOK * TOTAL_PROJ];
__device__ float g_Y3   [NTOK * 3 * D_MODEL];
__device__ float g_X2   [NTOK * 2 * D_MODEL];
__device__ float g_zb   [NTOK * D_MODEL];
__device__ float g_gate1[NTOK * D_MODEL];

__device__ __align__(256) bf16 g_in_h   [NTOK * D_MODEL], g_in_l   [NTOK * D_MODEL];
__device__ __align__(256) bf16 g_xn_h   [NTOK * D_MODEL], g_xn_l   [NTOK * D_MODEL];
__device__ __align__(256) bf16 g_core_h [NTOK * D_MODEL], g_core_l [NTOK * D_MODEL];
__device__ __align__(256) bf16 g_arelu_h[NTOK * D_MODEL], g_arelu_l[NTOK * D_MODEL];
__device__ __align__(256) bf16 g_rx_h   [NTOK * D_MODEL], g_rx_l   [NTOK * D_MODEL];
__device__ __align__(256) bf16 g_g1_h   [NTOK * D_MODEL], g_g1_l   [NTOK * D_MODEL];
__device__ __align__(256) bf16 g_ff_h   [NTOK * D_MODEL], g_ff_l   [NTOK * D_MODEL];
__device__ __align__(256) bf16 g_hid_h  [NTOK * D_FFC],   g_hid_l  [NTOK * D_FFC];

#define WPROJ_N (TOTAL_PROJ * D_MODEL)
#define WATTN_N (D_MODEL * D_MODEL)
#define WGRU_N  (3 * D_MODEL * D_MODEL)
#define WFFC1_N (D_FFC * D_MODEL)
#define WFFC2_N (D_MODEL * D_FFC)
__device__ __align__(256) bf16 g_wproj_h[WPROJ_N], g_wproj_l[WPROJ_N];
__device__ __align__(256) bf16 g_wattn_h[WATTN_N], g_wattn_l[WATTN_N];
__device__ __align__(256) bf16 g_g1w_h[WGRU_N], g_g1w_l[WGRU_N];
__device__ __align__(256) bf16 g_g1u_h[WGRU_N], g_g1u_l[WGRU_N];
__device__ __align__(256) bf16 g_g2w_h[WGRU_N], g_g2w_l[WGRU_N];
__device__ __align__(256) bf16 g_g2u_h[WGRU_N], g_g2u_l[WGRU_N];
__device__ __align__(256) bf16 g_fw1_h[WFFC1_N], g_fw1_l[WFFC1_N];
__device__ __align__(256) bf16 g_fw2_h[WFFC2_N], g_fw2_l[WFFC2_N];

__device__ __forceinline__ float sigf(float x) { return 1.0f / (1.0f + expf(-x)); }

__device__ __forceinline__ void split1(float v, bf16* h, bf16* l) {
    bf16 hv = __float2bfloat16(v);
    *h = hv;
    *l = __float2bfloat16(v - __bfloat162float(hv));
}

__device__ __forceinline__ void pack4(float4 v, uint2* hp, uint2* lp) {
    bf16 h0 = __float2bfloat16(v.x), h1 = __float2bfloat16(v.y);
    bf16 h2 = __float2bfloat16(v.z), h3 = __float2bfloat16(v.w);
    bf16 l0 = __float2bfloat16(v.x - __bfloat162float(h0));
    bf16 l1 = __float2bfloat16(v.y - __bfloat162float(h1));
    bf16 l2 = __float2bfloat16(v.z - __bfloat162float(h2));
    bf16 l3 = __float2bfloat16(v.w - __bfloat162float(h3));
    __nv_bfloat162 ha = __halves2bfloat162(h0, h1), hb = __halves2bfloat162(h2, h3);
    __nv_bfloat162 la = __halves2bfloat162(l0, l1), lb = __halves2bfloat162(l2, l3);
    uint2 hh, ll;
    hh.x = *reinterpret_cast<uint32_t*>(&ha);
    hh.y = *reinterpret_cast<uint32_t*>(&hb);
    ll.x = *reinterpret_cast<uint32_t*>(&la);
    ll.y = *reinterpret_cast<uint32_t*>(&lb);
    *hp = hh;
    *lp = ll;
}

__device__ __forceinline__ uint32_t smem_u32(const void* p) {
    uint32_t a;
    asm("{ .reg .u64 t; cvta.to.shared.u64 t, %1; cvt.u32.u64 %0, t; }"
        : "=r"(a) : "l"(p));
    return a;
}

__device__ __forceinline__ void cp16(uint32_t dst, const void* src) {
    asm volatile("cp.async.cg.shared.global [%0], [%1], 16;"
                 :: "r"(dst), "l"(src));
}
__device__ __forceinline__ void cp16z(uint32_t dst, const void* src, int sz) {
    asm volatile("cp.async.cg.shared.global [%0], [%1], 16, %2;"
                 :: "r"(dst), "l"(src), "r"(sz));
}
__device__ __forceinline__ void cp_commit() {
    asm volatile("cp.async.commit_group;" ::: "memory");
}

// ---------------------------------------------------------------------------
// GEMM problem descriptor (runtime args; up to 2 problems per launch)
// mode: 0 = fp32 out, 1 = relu?+bf16 hi/lo out, 2 = fused GRU-post
// ---------------------------------------------------------------------------
struct GArgs {
    const bf16 *Ah, *Al, *Bh, *Bl;
    const float* bias;
    float* Cf; bf16 *Ch; bf16 *Cl;
    const float *Yg, *zg, *xg;      // mode 2: Y3 (stride 1536), z, x
    float* outg; bf16 *oh; bf16 *ol;
    int N, K, act, mode, ntx;
};

template<int NT>
__device__ __forceinline__ void load_chunk_cp(
    uint32_t sb, const bf16* Ah, const bf16* Al,
    const bf16* Bh, const bf16* Bl,
    int bm, int bn, int N, int K, int k0, int tid)
{
    #pragma unroll
    for (int p = 0; p < 4; ++p) {
        int id = tid + p * 256;
        int row = id >> 3, grp = id & 7;
        uint32_t boff = (uint32_t)(row * 128 + grp * 16);
        uint32_t sw = boff ^ ((boff >> 3) & 0x70);
        size_t ao = (size_t)(bm + row) * K + k0 + grp * 8;
        cp16(sb + sw,         Ah + ao);
        cp16(sb + 16384 + sw, Al + ao);
    }
    const uint32_t bBh = sb + 32768;
    const uint32_t bBl = sb + 32768 + NT * 128;
    #pragma unroll
    for (int p = 0; p < NT / 32; ++p) {
        int id = tid + p * 256;
        int row = id >> 3, grp = id & 7;
        uint32_t boff = (uint32_t)(row * 128 + grp * 16);
        uint32_t sw = boff ^ ((boff >> 3) & 0x70);
        int brow = bn + row;
        int ok = (brow < N) ? 16 : 0;
        size_t bo = (size_t)(brow < N ? brow : 0) * K + k0 + grp * 8;
        cp16z(bBh + sw, Bh + bo, ok);
        cp16z(bBl + sw, Bl + bo, ok);
    }
    cp_commit();
}

#if HAS_TCGEN05
__device__ __forceinline__ uint32_t elect1() {
    uint32_t r;
    asm volatile("{\n\t.reg .pred p;\n\telect.sync _|p, 0xFFFFFFFF;\n\t"
                 "selp.b32 %0,1,0,p;\n\t}" : "=r"(r));
    return r;
}
__device__ __forceinline__ void tc_alloc(uint32_t saddr, uint32_t ncols) {
    asm volatile("tcgen05.alloc.cta_group::1.sync.aligned.shared::cta.b32 [%0], %1;"
                 :: "r"(saddr), "r"(ncols) : "memory");
}
__device__ __forceinline__ void tc_relinq() {
    asm volatile("tcgen05.relinquish_alloc_permit.cta_group::1.sync.aligned;");
}
__device__ __forceinline__ void tc_dealloc(uint32_t tmem, uint32_t ncols) {
    asm volatile("tcgen05.dealloc.cta_group::1.sync.aligned.b32 %0, %1;"
                 :: "r"(tmem), "r"(ncols));
}
__device__ __forceinline__ void mbar_init(uint32_t mb, uint32_t cnt) {
    asm volatile("mbarrier.init.shared.b64 [%0], %1;" :: "r"(mb), "r"(cnt) : "memory");
}
__device__ __forceinline__ void mbar_wait(uint32_t mb, uint32_t parity) {
    asm volatile("{\n\t.reg .pred P;\n\t"
                 "WL_%=:\n\t"
                 "mbarrier.try_wait.parity.acquire.cta.shared::cta.b64 P, [%0], %1, 0x989680;\n\t"
                 "@!P bra WL_%=;\n\t}"
                 :: "r"(mb), "r"(parity) : "memory");
}
__device__ __forceinline__ void tc_commit(uint32_t mb) {
    asm volatile("tcgen05.commit.cta_group::1.mbarrier::arrive::one.shared::cluster.b64 [%0];"
                 :: "r"(mb) : "memory");
}
__device__ __forceinline__ void fence_async_smem() {
    asm volatile("fence.proxy.async.shared::cta;" ::: "memory");
}
__device__ __forceinline__ void tc_fence_after() {
    asm volatile("tcgen05.fence::after_thread_sync;" ::: "memory");
}
__device__ __forceinline__ void tc_wait_ld() {
    asm volatile("tcgen05.wait::ld.sync.aligned;" ::: "memory");
}
__device__ __forceinline__ void mma_ss(uint32_t d, uint64_t a, uint64_t b,
                                       uint32_t idesc, bool en) {
    uint32_t e = en ? 1u : 0u;
    asm volatile("{\n\t.reg .pred p;\n\tsetp.ne.u32 p, %4, 0;\n\t"
                 "tcgen05.mma.cta_group::1.kind::f16 [%0], %1, %2, %3, "
                 "{%5, %5, %5, %5}, p;\n\t}"
                 :: "r"(d), "l"(a), "l"(b), "r"(idesc), "r"(e), "r"(0u)
                 : "memory");
}
__device__ __forceinline__ void ldtm32(uint32_t* r, uint32_t tmem) {
    asm volatile(
        "tcgen05.ld.sync.aligned.32x32b.x32.b32 "
        "{%0, %1, %2, %3, %4, %5, %6, %7, %8, %9, %10, %11, %12, %13, %14, %15, "
        "%16, %17, %18, %19, %20, %21, %22, %23, %24, %25, %26, %27, %28, %29, %30, %31}, [%32];"
        : "=r"(r[0]), "=r"(r[1]), "=r"(r[2]), "=r"(r[3]),
          "=r"(r[4]), "=r"(r[5]), "=r"(r[6]), "=r"(r[7]),
          "=r"(r[8]), "=r"(r[9]), "=r"(r[10]), "=r"(r[11]),
          "=r"(r[12]), "=r"(r[13]), "=r"(r[14]), "=r"(r[15]),
          "=r"(r[16]), "=r"(r[17]), "=r"(r[18]), "=r"(r[19]),
          "=r"(r[20]), "=r"(r[21]), "=r"(r[22]), "=r"(r[23]),
          "=r"(r[24]), "=r"(r[25]), "=r"(r[26]), "=r"(r[27]),
          "=r"(r[28]), "=r"(r[29]), "=r"(r[30]), "=r"(r[31])
        : "r"(tmem));
}
__device__ __forceinline__ uint64_t mk_desc(uint32_t saddr) {
    const uint64_t base = (uint64_t(2) << 61) | (uint64_t(1) << 46)
                        | (uint64_t(64) << 32) | (uint64_t(1) << 16);
    return base | ((uint64_t)(saddr >> 4) & 0x3FFF);
}
#define IDESC_128 ((1u << 4) | (1u << 7) | (1u << 10) | (16u << 17) | (8u << 24))
#endif // HAS_TCGEN05

__device__ __forceinline__ void mma16816(float* d, uint32_t a0, uint32_t a1,
                                         uint32_t a2, uint32_t a3,
                                         uint32_t b0, uint32_t b1) {
    asm volatile(
        "mma.sync.aligned.m16n8k16.row.col.f32.bf16.bf16.f32 "
        "{%0,%1,%2,%3}, {%4,%5,%6,%7}, {%8,%9}, {%0,%1,%2,%3};"
        : "+f"(d[0]), "+f"(d[1]), "+f"(d[2]), "+f"(d[3])
        : "r"(a0), "r"(a1), "r"(a2), "r"(a3), "r"(b0), "r"(b1));
}

// Shared epilogue element handler
__device__ __forceinline__ void epi_store(const GArgs& a, int row, int col,
                                          float v)
{
    if (a.bias) v += a.bias[col];
    if (a.act) v = fmaxf(v, 0.0f);
    size_t idx = (size_t)row * a.N + col;
    if (a.mode == 0) {
        a.Cf[idx] = v;
    } else if (a.mode == 1) {
        bf16 h = __float2bfloat16(v);
        a.Ch[idx] = h;
        a.Cl[idx] = __float2bfloat16(v - __bfloat162float(h));
    } else {
        // fused GRU post: v = RX value; N == 512
        float yv = a.Yg[(size_t)row * 1536 + 1024 + col];
        float hh = tanhf(yv + v);
        size_t e = (size_t)row * 512 + col;
        float zz = a.zg[e];
        float o = (1.0f - zz) * a.xg[e] + zz * hh;
        a.outg[e] = o;
        if (a.oh) split1(o, a.oh + e, a.ol + e);
    }
}

// ---------------------------------------------------------------------------
// Unified bf16-split GEMM, up to 2 problems per launch (blockIdx.z).
// Tile 128xNT, K-chunk 64, 2-stage cp.async pipeline.
// ---------------------------------------------------------------------------
#define STAGE_B(NT) (32768 + 2 * (NT) * 128)
#define SMEM_G(NT)  (1024 + 2 * STAGE_B(NT) + 1024)

template<int NT>
__global__ __launch_bounds__(256)
void gemm_tc(GArgs a0, GArgs a1)
{
    const GArgs a = (blockIdx.z == 0) ? a0 : a1;
    if ((int)blockIdx.x >= a.ntx) return;

    extern __shared__ char dsm[];
    const uint32_t sraw = smem_u32(dsm);
    const uint32_t tile0 = (sraw + 1024u) & ~1023u;
    const uint32_t off0 = tile0 - sraw;
    const uint32_t STG = STAGE_B(NT);

    const int tid = threadIdx.x;
    const int wid = tid >> 5, lid = tid & 31;
    const int bm = blockIdx.y * 128;
    const int bn = blockIdx.x * NT;
    char* smc = dsm;
    const int nk = a.K >> 6;

#if HAS_TCGEN05
    const uint32_t mb0 = sraw + 8, mb1 = sraw + 16;

    if (wid == 0) { tc_alloc(sraw, (NT > 128) ? 256 : 128); tc_relinq(); }
    if (tid == 0) { mbar_init(mb0, 1); mbar_init(mb1, 1); }
    __syncthreads();
    uint32_t tmem;
    asm volatile("ld.shared.b32 %0, [%1];" : "=r"(tmem) : "r"(sraw));

    load_chunk_cp<NT>(tile0, a.Ah, a.Al, a.Bh, a.Bl, bm, bn, a.N, a.K, 0, tid);

    int ph0 = 0, ph1 = 0;
    for (int k = 0; k < nk; ++k) {
        const int s = k & 1;
        if (k + 1 < nk) {
            if (k >= 1) {
                if (((k + 1) & 1) == 0) { mbar_wait(mb0, ph0); ph0 ^= 1; }
                else                    { mbar_wait(mb1, ph1); ph1 ^= 1; }
            }
            load_chunk_cp<NT>(tile0 + ((k + 1) & 1) * STG,
                              a.Ah, a.Al, a.Bh, a.Bl, bm, bn, a.N, a.K,
                              (k + 1) * 64, tid);
            asm volatile("cp.async.wait_group 1;" ::: "memory");
        } else {
            asm volatile("cp.async.wait_group 0;" ::: "memory");
        }
        fence_async_smem();
        __syncthreads();

        if (wid == 0) {
            if (elect1()) {
                uint32_t base = tile0 + s * STG;
                uint64_t dah = mk_desc(base);
                uint64_t dal = mk_desc(base + 16384);
                uint64_t dbh = mk_desc(base + 32768);
                uint64_t dbl = mk_desc(base + 32768 + NT * 128);
                #pragma unroll
                for (int ks = 0; ks < 4; ++ks) {
                    uint64_t o = (uint64_t)(ks * 2);
                    bool en0 = (k > 0) || (ks > 0);
                    mma_ss(tmem, dah + o, dbh + o, IDESC_128, en0);
                    mma_ss(tmem, dah + o, dbl + o, IDESC_128, true);
                    mma_ss(tmem, dal + o, dbh + o, IDESC_128, true);
                    if (NT > 128) {
                        mma_ss(tmem + 128, dah + o, dbh + 1024 + o, IDESC_128, en0);
                        mma_ss(tmem + 128, dah + o, dbl + 1024 + o, IDESC_128, true);
                        mma_ss(tmem + 128, dal + o, dbh + 1024 + o, IDESC_128, true);
                    }
                }
                tc_commit(s == 0 ? mb0 : mb1);
            }
        }
    }
    if (((nk - 1) & 1) == 0) mbar_wait(mb0, ph0);
    else                     mbar_wait(mb1, ph1);
    tc_fence_after();
    __syncthreads();

    // Coalesced epilogue via smem transpose
    float* sf = (float*)(smc + off0);
    #pragma unroll
    for (int nb = 0; nb < NT / 32; ++nb) {
        if (wid < 4) {
            uint32_t dr[32];
            ldtm32(dr, tmem + nb * 32);
            tc_wait_ld();
            int mrow = wid * 32 + lid;
            #pragma unroll
            for (int c = 0; c < 32; ++c) sf[mrow * 33 + c] = __uint_as_float(dr[c]);
        }
        __syncthreads();
        int cb = bn + nb * 32;
        if (cb < a.N) {
            int col = cb + lid;
            if (col < a.N) {
                int rbase = (tid >> 5) * 16;
                #pragma unroll
                for (int rr = 0; rr < 16; ++rr) {
                    int row = rbase + rr;
                    epi_store(a, bm + row, col, sf[row * 33 + lid]);
                }
            }
        }
        __syncthreads();
    }
    if (wid == 0) tc_dealloc(tmem, (NT > 128) ? 256 : 128);

#else  // ------------------- mma.sync fallback path -------------------------
    const int NTW = NT / 4;
    const int NNT = NT / 32;
    const int wm0 = (wid >> 2) * 64;
    const int wn0 = (wid & 3) * NTW;
    const int g = lid >> 2, tg = lid & 3;

    float acc[4][NT / 32][4];
    #pragma unroll
    for (int x = 0; x < 4; ++x)
        #pragma unroll
        for (int y = 0; y < NNT; ++y)
            #pragma unroll
            for (int c = 0; c < 4; ++c) acc[x][y][c] = 0.0f;

    load_chunk_cp<NT>(tile0, a.Ah, a.Al, a.Bh, a.Bl, bm, bn, a.N, a.K, 0, tid);

    for (int k = 0; k < nk; ++k) {
        const uint32_t oS = off0 + (uint32_t)(k & 1) * STG;
        if (k + 1 < nk) {
            load_chunk_cp<NT>(tile0 + ((k + 1) & 1) * STG,
                              a.Ah, a.Al, a.Bh, a.Bl, bm, bn, a.N, a.K,
                              (k + 1) * 64, tid);
            asm volatile("cp.async.wait_group 1;" ::: "memory");
        } else {
            asm volatile("cp.async.wait_group 0;" ::: "memory");
        }
        __syncthreads();

        const uint32_t oA_h = oS, oA_l = oS + 16384;
        const uint32_t oB_h = oS + 32768, oB_l = oS + 32768 + NT * 128;

        #pragma unroll
        for (int ks = 0; ks < 4; ++ks) {
            const uint32_t kb = (uint32_t)(ks * 32 + tg * 4);
            uint32_t bh0[NT / 32], bh1[NT / 32], bl0[NT / 32], bl1[NT / 32];
            #pragma unroll
            for (int nt = 0; nt < NNT; ++nt) {
                uint32_t row = (uint32_t)(wn0 + nt * 8 + g);
                uint32_t o1 = row * 128 + kb;
                uint32_t o2 = o1 + 16;
                uint32_t s1 = o1 ^ ((o1 >> 3) & 0x70);
                uint32_t s2 = o2 ^ ((o2 >> 3) & 0x70);
                bh0[nt] = *(const uint32_t*)(smc + oB_h + s1);
                bh1[nt] = *(const uint32_t*)(smc + oB_h + s2);
                bl0[nt] = *(const uint32_t*)(smc + oB_l + s1);
                bl1[nt] = *(const uint32_t*)(smc + oB_l + s2);
            }
            #pragma unroll
            for (int mt = 0; mt < 4; ++mt) {
                uint32_t r0 = (uint32_t)(wm0 + mt * 16 + g);
                uint32_t o_r0c0 = r0 * 128 + kb;
                uint32_t o_r8c0 = o_r0c0 + 8 * 128;
                uint32_t o_r0c8 = o_r0c0 + 16;
                uint32_t o_r8c8 = o_r8c0 + 16;
                uint32_t s00 = o_r0c0 ^ ((o_r0c0 >> 3) & 0x70);
                uint32_t s80 = o_r8c0 ^ ((o_r8c0 >> 3) & 0x70);
                uint32_t s08 = o_r0c8 ^ ((o_r0c8 >> 3) & 0x70);
                uint32_t s88 = o_r8c8 ^ ((o_r8c8 >> 3) & 0x70);
                uint32_t ah0 = *(const uint32_t*)(smc + oA_h + s00);
                uint32_t ah1 = *(const uint32_t*)(smc + oA_h + s80);
                uint32_t ah2 = *(const uint32_t*)(smc + oA_h + s08);
                uint32_t ah3 = *(const uint32_t*)(smc + oA_h + s88);
                uint32_t al0 = *(const uint32_t*)(smc + oA_l + s00);
                uint32_t al1 = *(const uint32_t*)(smc + oA_l + s80);
                uint32_t al2 = *(const uint32_t*)(smc + oA_l + s08);
                uint32_t al3 = *(const uint32_t*)(smc + oA_l + s88);
                #pragma unroll
                for (int nt = 0; nt < NNT; ++nt) {
                    mma16816(acc[mt][nt], ah0, ah1, ah2, ah3, bh0[nt], bh1[nt]);
                    mma16816(acc[mt][nt], ah0, ah1, ah2, ah3, bl0[nt], bl1[nt]);
                    mma16816(acc[mt][nt], al0, al1, al2, al3, bh0[nt], bh1[nt]);
                }
            }
        }
        __syncthreads();
    }

    #pragma unroll
    for (int mt = 0; mt < 4; ++mt) {
        #pragma unroll
        for (int nt = 0; nt < NNT; ++nt) {
            int r0 = bm + wm0 + mt * 16 + g;
            int c0 = bn + wn0 + nt * 8 + tg * 2;
            #pragma unroll
            for (int half = 0; half < 2; ++half) {
                int row = r0 + half * 8;
                #pragma unroll
                for (int cc = 0; cc < 2; ++cc) {
                    int col = c0 + cc;
                    if (col < a.N)
                        epi_store(a, row, col, acc[mt][nt][half * 2 + cc]);
                }
            }
        }
    }
#endif
}

// ---------------------------------------------------------------------------
// Mega weight split: all 8 weight tensors in one launch
// ---------------------------------------------------------------------------
struct SArgs {
    const float4* s[8];
    uint2* h[8];
    uint2* l[8];
    int off[9];   // cumulative vec4 offsets
};

__global__ __launch_bounds__(256)
void wsplit_all(SArgs a)
{
    int i = blockIdx.x * 256 + threadIdx.x;
    #pragma unroll
    for (int k = 0; k < 8; ++k) {
        if (i >= a.off[k] && i < a.off[k + 1]) {
            int j = i - a.off[k];
            pack4(a.s[k][j], a.h[k] + j, a.l[k] + j);
        }
    }
}

// ---------------------------------------------------------------------------
// LayerNorm (+ optional raw-input hi/lo split emission)
// ---------------------------------------------------------------------------
__global__ __launch_bounds__(256)
void ln_kernel(const float* __restrict__ x, const float* __restrict__ g,
               const float* __restrict__ b, bf16* __restrict__ yh,
               bf16* __restrict__ yl, bf16* __restrict__ rh,
               bf16* __restrict__ rl)
{
    __shared__ float rbuf[8];
    __shared__ float smean, srstd;
    const int row = blockIdx.x;
    const int tid = threadIdx.x;
    const int lane = tid & 31, warp = tid >> 5;
    const float* xr = x + (size_t)row * D_MODEL;

    float v0 = xr[tid], v1 = xr[tid + 256];
    size_t base = (size_t)row * D_MODEL;
    if (rh) {
        split1(v0, rh + base + tid,       rl + base + tid);
        split1(v1, rh + base + tid + 256, rl + base + tid + 256);
    }

    float s = v0 + v1;
    #pragma unroll
    for (int o = 16; o; o >>= 1) s += __shfl_down_sync(0xffffffffu, s, o);
    if (!lane) rbuf[warp] = s;
    __syncthreads();
    if (warp == 0) {
        float t = (lane < 8) ? rbuf[lane] : 0.0f;
        #pragma unroll
        for (int o = 4; o; o >>= 1) t += __shfl_down_sync(0xffffffffu, t, o);
        if (!lane) smean = t * (1.0f / D_MODEL);
    }
    __syncthreads();
    float m = smean;

    float d0 = v0 - m, d1 = v1 - m;
    float sv = d0 * d0 + d1 * d1;
    #pragma unroll
    for (int o = 16; o; o >>= 1) sv += __shfl_down_sync(0xffffffffu, sv, o);
    if (!lane) rbuf[warp] = sv;
    __syncthreads();
    if (warp == 0) {
        float t = (lane < 8) ? rbuf[lane] : 0.0f;
        #pragma unroll
        for (int o = 4; o; o >>= 1) t += __shfl_down_sync(0xffffffffu, t, o);
        if (!lane) srstd = rsqrtf(t * (1.0f / D_MODEL) + 1e-5f);
    }
    __syncthreads();
    float r = srstd;

    float o0 = d0 * r * g[tid]       + b[tid];
    float o1 = d1 * r * g[tid + 256] + b[tid + 256];
    split1(o0, yh + base + tid,       yl + base + tid);
    split1(o1, yh + base + tid + 256, yl + base + tid + 256);
}

// ---------------------------------------------------------------------------
// Fused scan + attention-core kernel
// ---------------------------------------------------------------------------
__global__ __launch_bounds__(256)
void scan_kernel(const float* __restrict__ allproj, const int* __restrict__ terms,
                 const float* __restrict__ tick, const float* __restrict__ tk,
                 const float* __restrict__ tv, const float* __restrict__ s_prev,
                 bf16* __restrict__ core_h, bf16* __restrict__ core_l)
{
    const int bh = blockIdx.x;
    const int b = bh >> 3, h = bh & 7;
    const int tid = threadIdx.x;
    const int lane = tid & 31, warp = tid >> 5;

    __shared__ float sk[64], sq[64], sv[64], sb[64], sg[64];
    __shared__ float sp[12], socc[8];
    __shared__ float red[9 * 8];
    __shared__ float kdqn[9];
    __shared__ float kvpart[256];
    __shared__ float sterm;

    const int d  = tid >> 2, j = tid & 3;
    const int d2 = tid & 63, r0 = tid >> 6;

    float Kst[8], S, V0, V1;
    #pragma unroll
    for (int r = 0; r < 8; ++r)
        Kst[r] = tk[(((size_t)b * R_ + r) * H_ + h) * 256 + tid];
    S  = s_prev[((size_t)b * H_ + h) * 256 + tid];
    V0 = tv[(((size_t)b * R_ + r0    ) * H_ + h) * 64 + d2];
    V1 = tv[(((size_t)b * R_ + r0 + 4) * H_ + h) * 64 + d2];
    const float tickb = tick[b];

    for (int t = 0; t < T_; ++t) {
        const size_t rowbase = ((size_t)t * B_ + b) * TOTAL_PROJ;
        const float* ap = allproj + rowbase + h * 320;
        if (tid < 64) {
            sk[tid] = ap[tid];
            sq[tid] = ap[64 + tid];
            sv[tid] = ap[128 + tid];
            sb[tid] = ap[192 + tid];
            sg[tid] = ap[256 + tid];
        } else if (tid < 76) {
            sp[tid - 64] = allproj[rowbase + KQV_DIM + h * 12 + (tid - 64)];
        } else if (tid >= 96 && tid < 104) {
            int u = tid - 96;
            float om = -3.14159265358979323846f
                     + (float)u * (6.28318530717958647692f / 7.0f);
            socc[u] = cosf((tickb + (float)(t + 1)) * om);
        } else if (tid == 255) {
            sterm = 1.0f - (float)terms[t * B_ + b];
        }
        __syncthreads();

        const float term = sterm;

        float ke = fmaxf(sk[d], 0.0f) * fmaxf(sp[j], 0.0f);
        float qe = fmaxf(sq[d], 0.0f) * fmaxf(sp[4 + j], 0.0f);
        float ge = sigf(sg[d]) * sigf(sp[8 + j]);
        float kg = ke * ge;
        float dg = (1.0f - ge) * term;
        S = fmaf(dg, S, kg);
        float loc[9];
        #pragma unroll
        for (int r = 0; r < 8; ++r) {
            Kst[r] = fmaf(dg, Kst[r], kg * socc[r]);
            loc[r] = Kst[r] * qe;
        }
        loc[8] = S * qe;

        float bs = sigf(sb[d2]);
        float vg = sv[d2] * bs;
        float db = (1.0f - bs) * term;
        V0 = fmaf(db, V0, vg * socc[r0]);
        V1 = fmaf(db, V1, vg * socc[r0 + 4]);

        #pragma unroll
        for (int v = 0; v < 9; ++v) {
            float x = loc[v];
            x += __shfl_down_sync(0xffffffffu, x, 16);
            x += __shfl_down_sync(0xffffffffu, x, 8);
            x += __shfl_down_sync(0xffffffffu, x, 4);
            x += __shfl_down_sync(0xffffffffu, x, 2);
            x += __shfl_down_sync(0xffffffffu, x, 1);
            if (lane == 0) red[v * 8 + warp] = x;
        }
        __syncthreads();
        if (tid < 9) {
            float s = 0.0f;
            #pragma unroll
            for (int w = 0; w < 8; ++w) s += red[tid * 8 + w];
            kdqn[tid] = (tid == 8) ? (s + 1e-6f) : s;
        }
        __syncthreads();

        kvpart[tid] = V0 * kdqn[r0] + V1 * kdqn[r0 + 4];
        __syncthreads();
        if (tid < 64) {
            float kv = kvpart[tid] + kvpart[64 + tid]
                     + kvpart[128 + tid] + kvpart[192 + tid];
            float val = kv / (16.0f * kdqn[8]);
            size_t idx = ((size_t)t * B_ + b) * D_MODEL + h * 64 + tid;
            split1(val, core_h + idx, core_l + idx);
        }
        __syncthreads();
    }
}

// ---------------------------------------------------------------------------
// GRU stage 1 (vectorized): r, z, rx
// ---------------------------------------------------------------------------
__global__ __launch_bounds__(256)
void gru_pre(const float4* __restrict__ x, const float* __restrict__ Y3,
             const float* __restrict__ X2, uint2* __restrict__ rxh,
             uint2* __restrict__ rxl, float4* __restrict__ z, int n4)
{
    int i = blockIdx.x * 256 + threadIdx.x;
    if (i >= n4) return;
    int row = i >> 7, c = (i & 127) * 4;
    const float4 y0 = *(const float4*)&Y3[(size_t)row * 1536 + c];
    const float4 y1 = *(const float4*)&Y3[(size_t)row * 1536 + 512 + c];
    const float4 x0 = *(const float4*)&X2[(size_t)row * 1024 + c];
    const float4 x1 = *(const float4*)&X2[(size_t)row * 1024 + 512 + c];
    float4 xv = x[i];
    float4 zz;
    zz.x = sigf(y1.x + x1.x - 2.0f);
    zz.y = sigf(y1.y + x1.y - 2.0f);
    zz.z = sigf(y1.z + x1.z - 2.0f);
    zz.w = sigf(y1.w + x1.w - 2.0f);
    float4 rx;
    rx.x = sigf(y0.x + x0.x) * xv.x;
    rx.y = sigf(y0.y + x0.y) * xv.y;
    rx.z = sigf(y0.z + x0.z) * xv.z;
    rx.w = sigf(y0.w + x0.w) * xv.w;
    z[i] = zz;
    pack4(rx, rxh + i, rxl + i);
}

// ---------------------------------------------------------------------------
// Launch
// ---------------------------------------------------------------------------
template<typename Tp>
static Tp* symptr(const void* sym) {
    void* p = nullptr;
    cudaGetSymbolAddress(&p, sym);
    return (Tp*)p;
}

static GArgs mkG(const bf16* Ah, const bf16* Al, const bf16* Bh, const bf16* Bl,
                 const float* bias, float* Cf, bf16* Ch, bf16* Cl,
                 int N, int K, int act, int mode, int ntx)
{
    GArgs a;
    a.Ah = Ah; a.Al = Al; a.Bh = Bh; a.Bl = Bl;
    a.bias = bias; a.Cf = Cf; a.Ch = Ch; a.Cl = Cl;
    a.Yg = nullptr; a.zg = nullptr; a.xg = nullptr;
    a.outg = nullptr; a.oh = nullptr; a.ol = nullptr;
    a.N = N; a.K = K; a.act = act; a.mode = mode; a.ntx = ntx;
    return a;
}

extern "C" void kernel_launch(void* const* d_in, const int* in_sizes, int n_in,
                              void* d_out, int out_size)
{
    const float* inputs   = (const float*)d_in[0];
    const int*   terms    = (const int*)  d_in[1];
    const float* tilde_k  = (const float*)d_in[2];
    const float* tilde_v  = (const float*)d_in[3];
    const float* s_prev   = (const float*)d_in[4];
    const float* tick     = (const float*)d_in[5];
    const float* w_proj   = (const float*)d_in[6];
    const float* b_proj   = (const float*)d_in[7];
    const float* w_attn   = (const float*)d_in[8];
    const float* b_attn   = (const float*)d_in[9];
    const float* ln1_g    = (const float*)d_in[10];
    const float* ln1_b    = (const float*)d_in[11];
    const float* ln2_g    = (const float*)d_in[12];
    const float* ln2_b    = (const float*)d_in[13];
    const float* gru1_w   = (const float*)d_in[14];
    const float* gru1_u   = (const float*)d_in[15];
    const float* gru2_w   = (const float*)d_in[16];
    const float* gru2_u   = (const float*)d_in[17];
    const float* ffc_w1   = (const float*)d_in[18];
    const float* ffc_b1   = (const float*)d_in[19];
    const float* ffc_w2   = (const float*)d_in[20];
    const float* ffc_b2   = (const float*)d_in[21];
    float* out = (float*)d_out;

    float* allproj = symptr<float>(g_allproj);
    float* Y3   = symptr<float>(g_Y3);
    float* X2   = symptr<float>(g_X2);
    float* zb   = symptr<float>(g_zb);
    float* gate1= symptr<float>(g_gate1);

    bf16 *in_h = symptr<bf16>(g_in_h),  *in_l = symptr<bf16>(g_in_l);
    bf16 *xn_h = symptr<bf16>(g_xn_h),  *xn_l = symptr<bf16>(g_xn_l);
    bf16 *co_h = symptr<bf16>(g_core_h),*co_l = symptr<bf16>(g_core_l);
    bf16 *ar_h = symptr<bf16>(g_arelu_h),*ar_l= symptr<bf16>(g_arelu_l);
    bf16 *rx_h = symptr<bf16>(g_rx_h),  *rx_l = symptr<bf16>(g_rx_l);
    bf16 *g1_h = symptr<bf16>(g_g1_h),  *g1_l = symptr<bf16>(g_g1_l);
    bf16 *ff_h = symptr<bf16>(g_ff_h),  *ff_l = symptr<bf16>(g_ff_l);
    bf16 *hd_h = symptr<bf16>(g_hid_h), *hd_l = symptr<bf16>(g_hid_l);

    bf16 *wp_h = symptr<bf16>(g_wproj_h), *wp_l = symptr<bf16>(g_wproj_l);
    bf16 *wa_h = symptr<bf16>(g_wattn_h), *wa_l = symptr<bf16>(g_wattn_l);
    bf16 *w1w_h= symptr<bf16>(g_g1w_h),   *w1w_l= symptr<bf16>(g_g1w_l);
    bf16 *w1u_h= symptr<bf16>(g_g1u_h),   *w1u_l= symptr<bf16>(g_g1u_l);
    bf16 *w2w_h= symptr<bf16>(g_g2w_h),   *w2w_l= symptr<bf16>(g_g2w_l);
    bf16 *w2u_h= symptr<bf16>(g_g2u_h),   *w2u_l= symptr<bf16>(g_g2u_l);
    bf16 *f1_h = symptr<bf16>(g_fw1_h),   *f1_l = symptr<bf16>(g_fw1_l);
    bf16 *f2_h = symptr<bf16>(g_fw2_h),   *f2_l = symptr<bf16>(g_fw2_l);

    cudaFuncSetAttribute(gemm_tc<128>, cudaFuncAttributeMaxDynamicSharedMemorySize, SMEM_G(128));
    cudaFuncSetAttribute(gemm_tc<256>, cudaFuncAttributeMaxDynamicSharedMemorySize, SMEM_G(256));

    const int n = NTOK * D_MODEL;
    const int n4 = n / 4;
    dim3 thr(256);
    const int eg4 = (n4 + 255) / 256;
    const int OFF2 = 2 * D_MODEL * D_MODEL;
    GArgs nil = mkG(nullptr,nullptr,nullptr,nullptr,nullptr,nullptr,nullptr,
                    nullptr, 0, 64, 0, 0, 0);

    // 1) ln1 + raw input split
    ln_kernel<<<NTOK, thr>>>(inputs, ln1_g, ln1_b, xn_h, xn_l, in_h, in_l);

    // 2) all weight splits in one launch
    {
        SArgs sa;
        const float* srcs[8] = {w_proj, w_attn, gru1_w, gru1_u,
                                gru2_w, gru2_u, ffc_w1, ffc_w2};
        bf16* hs[8] = {wp_h, wa_h, w1w_h, w1u_h, w2w_h, w2u_h, f1_h, f2_h};
        bf16* ls[8] = {wp_l, wa_l, w1w_l, w1u_l, w2w_l, w2u_l, f1_l, f2_l};
        int cnts[8] = {WPROJ_N, WATTN_N, WGRU_N, WGRU_N,
                       WGRU_N, WGRU_N, WFFC1_N, WFFC2_N};
        int acc = 0;
        for (int k = 0; k < 8; ++k) {
            sa.s[k] = (const float4*)srcs[k];
            sa.h[k] = (uint2*)hs[k];
            sa.l[k] = (uint2*)ls[k];
            sa.off[k] = acc;
            acc += cnts[k] / 4;
        }
        sa.off[8] = acc;
        wsplit_all<<<(acc + 255) / 256, thr>>>(sa);
    }

    // 3) proj GEMM (NT=256)
    {
        GArgs a = mkG(xn_h, xn_l, wp_h, wp_l, b_proj, allproj, nullptr, nullptr,
                      TOTAL_PROJ, D_MODEL, 0, 0, (TOTAL_PROJ + 255) / 256);
        gemm_tc<256><<<dim3(a.ntx, 32, 1), thr, SMEM_G(256)>>>(a, nil);
    }

    // 4) scan
    scan_kernel<<<B_ * H_, thr>>>(allproj, terms, tick, tilde_k, tilde_v,
                                  s_prev, co_h, co_l);

    // 5) dual: attn (relu, hi/lo) + GRU1 X2 (NT=128)
    {
        GArgs a0 = mkG(co_h, co_l, wa_h, wa_l, b_attn, nullptr, ar_h, ar_l,
                       D_MODEL, D_MODEL, 1, 1, 4);
        GArgs a1 = mkG(in_h, in_l, w1u_h, w1u_l, nullptr, X2, nullptr, nullptr,
                       2 * D_MODEL, D_MODEL, 0, 0, 8);
        gemm_tc<128><<<dim3(8, 32, 2), thr, SMEM_G(128)>>>(a0, a1);
    }

    // 6) GRU1 Y3 (NT=256)
    {
        GArgs a = mkG(ar_h, ar_l, w1w_h, w1w_l, nullptr, Y3, nullptr, nullptr,
                      3 * D_MODEL, D_MODEL, 0, 0, 6);
        gemm_tc<256><<<dim3(6, 32, 1), thr, SMEM_G(256)>>>(a, nil);
    }

    // 7) gru_pre 1
    gru_pre<<<eg4, thr>>>((const float4*)inputs, Y3, X2,
                          (uint2*)rx_h, (uint2*)rx_l, (float4*)zb, n4);

    // 8) RX GEMM + fused gru_post -> gate1 (+hi/lo)
    {
        GArgs a = mkG(rx_h, rx_l, w1u_h + OFF2, w1u_l + OFF2, nullptr,
                      nullptr, nullptr, nullptr, D_MODEL, D_MODEL, 0, 2, 4);
        a.Yg = Y3; a.zg = zb; a.xg = inputs;
        a.outg = gate1; a.oh = g1_h; a.ol = g1_l;
        gemm_tc<128><<<dim3(4, 32, 1), thr, SMEM_G(128)>>>(a, nil);
    }

    // 9) ln2
    ln_kernel<<<NTOK, thr>>>(gate1, ln2_g, ln2_b, xn_h, xn_l, nullptr, nullptr);

    // 10) dual: FFC1 (relu, hi/lo) + GRU2 X2 (NT=256)
    {
        GArgs a0 = mkG(xn_h, xn_l, f1_h, f1_l, ffc_b1, nullptr, hd_h, hd_l,
                       D_FFC, D_MODEL, 1, 1, 8);
        GArgs a1 = mkG(g1_h, g1_l, w2u_h, w2u_l, nullptr, X2, nullptr, nullptr,
                       2 * D_MODEL, D_MODEL, 0, 0, 4);
        gemm_tc<256><<<dim3(8, 32, 2), thr, SMEM_G(256)>>>(a0, a1);
    }

    // 11) FFC2 (relu, hi/lo) (NT=128, K=2048)
    {
        GArgs a = mkG(hd_h, hd_l, f2_h, f2_l, ffc_b2, nullptr, ff_h, ff_l,
                      D_MODEL, D_FFC, 1, 1, 4);
        gemm_tc<128><<<dim3(4, 32, 1), thr, SMEM_G(128)>>>(a, nil);
    }

    // 12) GRU2 Y3 (NT=256)
    {
        GArgs a = mkG(ff_h, ff_l, w2w_h, w2w_l, nullptr, Y3, nullptr, nullptr,
                      3 * D_MODEL, D_MODEL, 0, 0, 6);
        gemm_tc<256><<<dim3(6, 32, 1), thr, SMEM_G(256)>>>(a, nil);
    }

    // 13) gru_pre 2
    gru_pre<<<eg4, thr>>>((const float4*)gate1, Y3, X2,
                          (uint2*)rx_h, (uint2*)rx_l, (float4*)zb, n4);

    // 14) RX GEMM + fused gru_post -> out
    {
        GArgs a = mkG(rx_h, rx_l, w2u_h + OFF2, w2u_l + OFF2, nullptr,
                      nullptr, nullptr, nullptr, D_MODEL, D_MODEL, 0, 2, 4);
        a.Yg = Y3; a.zg = zb; a.xg = gate1;
        a.outg = out; a.oh = nullptr; a.ol = nullptr;
        gemm_tc<128><<<dim3(4, 32, 1), thr, SMEM_G(128)>>>(a, nil);
    }
}

// round 11
// speedup vs baseline: 1.8122x; 1.8122x over previous
#include <cuda_runtime.h>
#include <cuda_bf16.h>
#include <math.h>
#include <stdint.h>

// Problem constants
#define D_MODEL 512
#define H_ 8
#define HD_ 64
#define ETA_ 4
#define R_ 8
#define D_FFC 2048
#define T_ 128
#define B_ 32
#define NTOK (T_*B_)            // 4096
#define TOTAL_PROJ 2656
#define KQV_DIM 2560

typedef __nv_bfloat16 bf16;

#if defined(__CUDA_ARCH_FEAT_SM103_ALL) || defined(__CUDA_ARCH_FEAT_SM100_ALL)
#define HAS_TCGEN05 1
#else
#define HAS_TCGEN05 0
#endif

// ---------------------------------------------------------------------------
// Scratch
// ---------------------------------------------------------------------------
__device__ float g_allproj[NTOK * TOTAL_PROJ];
__device__ float g_Y3   [NTOK * 3 * D_MODEL];
__device__ float g_X2   [NTOK * 2 * D_MODEL];
__device__ float g_zb   [NTOK * D_MODEL];
__device__ float g_gate1[NTOK * D_MODEL];

__device__ __align__(256) bf16 g_in_h   [NTOK * D_MODEL], g_in_l   [NTOK * D_MODEL];
__device__ __align__(256) bf16 g_xn_h   [NTOK * D_MODEL], g_xn_l   [NTOK * D_MODEL];
__device__ __align__(256) bf16 g_core_h [NTOK * D_MODEL], g_core_l [NTOK * D_MODEL];
__device__ __align__(256) bf16 g_arelu_h[NTOK * D_MODEL], g_arelu_l[NTOK * D_MODEL];
__device__ __align__(256) bf16 g_rx_h   [NTOK * D_MODEL], g_rx_l   [NTOK * D_MODEL];
__device__ __align__(256) bf16 g_g1_h   [NTOK * D_MODEL], g_g1_l   [NTOK * D_MODEL];
__device__ __align__(256) bf16 g_ff_h   [NTOK * D_MODEL], g_ff_l   [NTOK * D_MODEL];
__device__ __align__(256) bf16 g_hid_h  [NTOK * D_FFC],   g_hid_l  [NTOK * D_FFC];

#define WPROJ_N (TOTAL_PROJ * D_MODEL)
#define WATTN_N (D_MODEL * D_MODEL)
#define WGRU_N  (3 * D_MODEL * D_MODEL)
#define WFFC1_N (D_FFC * D_MODEL)
#define WFFC2_N (D_MODEL * D_FFC)
__device__ __align__(256) bf16 g_wproj_h[WPROJ_N], g_wproj_l[WPROJ_N];
__device__ __align__(256) bf16 g_wattn_h[WATTN_N], g_wattn_l[WATTN_N];
__device__ __align__(256) bf16 g_g1w_h[WGRU_N], g_g1w_l[WGRU_N];
__device__ __align__(256) bf16 g_g1u_h[WGRU_N], g_g1u_l[WGRU_N];
__device__ __align__(256) bf16 g_g2w_h[WGRU_N], g_g2w_l[WGRU_N];
__device__ __align__(256) bf16 g_g2u_h[WGRU_N], g_g2u_l[WGRU_N];
__device__ __align__(256) bf16 g_fw1_h[WFFC1_N], g_fw1_l[WFFC1_N];
__device__ __align__(256) bf16 g_fw2_h[WFFC2_N], g_fw2_l[WFFC2_N];

__device__ __forceinline__ float sigf(float x) { return 1.0f / (1.0f + expf(-x)); }

__device__ __forceinline__ void split1(float v, bf16* h, bf16* l) {
    bf16 hv = __float2bfloat16(v);
    *h = hv;
    *l = __float2bfloat16(v - __bfloat162float(hv));
}

__device__ __forceinline__ void pack4(float4 v, uint2* hp, uint2* lp) {
    bf16 h0 = __float2bfloat16(v.x), h1 = __float2bfloat16(v.y);
    bf16 h2 = __float2bfloat16(v.z), h3 = __float2bfloat16(v.w);
    bf16 l0 = __float2bfloat16(v.x - __bfloat162float(h0));
    bf16 l1 = __float2bfloat16(v.y - __bfloat162float(h1));
    bf16 l2 = __float2bfloat16(v.z - __bfloat162float(h2));
    bf16 l3 = __float2bfloat16(v.w - __bfloat162float(h3));
    __nv_bfloat162 ha = __halves2bfloat162(h0, h1), hb = __halves2bfloat162(h2, h3);
    __nv_bfloat162 la = __halves2bfloat162(l0, l1), lb = __halves2bfloat162(l2, l3);
    uint2 hh, ll;
    hh.x = *reinterpret_cast<uint32_t*>(&ha);
    hh.y = *reinterpret_cast<uint32_t*>(&hb);
    ll.x = *reinterpret_cast<uint32_t*>(&la);
    ll.y = *reinterpret_cast<uint32_t*>(&lb);
    *hp = hh;
    *lp = ll;
}

__device__ __forceinline__ uint32_t smem_u32(const void* p) {
    uint32_t a;
    asm("{ .reg .u64 t; cvta.to.shared.u64 t, %1; cvt.u32.u64 %0, t; }"
        : "=r"(a) : "l"(p));
    return a;
}

__device__ __forceinline__ void cp16(uint32_t dst, const void* src) {
    asm volatile("cp.async.cg.shared.global [%0], [%1], 16;"
                 :: "r"(dst), "l"(src));
}
__device__ __forceinline__ void cp16z(uint32_t dst, const void* src, int sz) {
    asm volatile("cp.async.cg.shared.global [%0], [%1], 16, %2;"
                 :: "r"(dst), "l"(src), "r"(sz));
}
__device__ __forceinline__ void cp4(uint32_t dst, const void* src) {
    asm volatile("cp.async.ca.shared.global [%0], [%1], 4;"
                 :: "r"(dst), "l"(src));
}
__device__ __forceinline__ void cp_commit() {
    asm volatile("cp.async.commit_group;" ::: "memory");
}

template<int NT>
__device__ __forceinline__ void load_chunk_cp(
    uint32_t sb, const bf16* Ah, const bf16* Al,
    const bf16* Bh, const bf16* Bl,
    int bm, int bn, int N, int K, int k0, int tid)
{
    #pragma unroll
    for (int p = 0; p < 4; ++p) {
        int id = tid + p * 256;
        int row = id >> 3, grp = id & 7;
        uint32_t boff = (uint32_t)(row * 128 + grp * 16);
        uint32_t sw = boff ^ ((boff >> 3) & 0x70);
        size_t ao = (size_t)(bm + row) * K + k0 + grp * 8;
        cp16(sb + sw,         Ah + ao);
        cp16(sb + 16384 + sw, Al + ao);
    }
    const uint32_t bBh = sb + 32768;
    const uint32_t bBl = sb + 32768 + NT * 128;
    #pragma unroll
    for (int p = 0; p < NT / 32; ++p) {
        int id = tid + p * 256;
        int row = id >> 3, grp = id & 7;
        uint32_t boff = (uint32_t)(row * 128 + grp * 16);
        uint32_t sw = boff ^ ((boff >> 3) & 0x70);
        int brow = bn + row;
        int ok = (brow < N) ? 16 : 0;
        size_t bo = (size_t)(brow < N ? brow : 0) * K + k0 + grp * 8;
        cp16z(bBh + sw, Bh + bo, ok);
        cp16z(bBl + sw, Bl + bo, ok);
    }
    cp_commit();
}

#if HAS_TCGEN05
__device__ __forceinline__ uint32_t elect1() {
    uint32_t r;
    asm volatile("{\n\t.reg .pred p;\n\telect.sync _|p, 0xFFFFFFFF;\n\t"
                 "selp.b32 %0,1,0,p;\n\t}" : "=r"(r));
    return r;
}
__device__ __forceinline__ void tc_alloc(uint32_t saddr, uint32_t ncols) {
    asm volatile("tcgen05.alloc.cta_group::1.sync.aligned.shared::cta.b32 [%0], %1;"
                 :: "r"(saddr), "r"(ncols) : "memory");
}
__device__ __forceinline__ void tc_relinq() {
    asm volatile("tcgen05.relinquish_alloc_permit.cta_group::1.sync.aligned;");
}
__device__ __forceinline__ void tc_dealloc(uint32_t tmem, uint32_t ncols) {
    asm volatile("tcgen05.dealloc.cta_group::1.sync.aligned.b32 %0, %1;"
                 :: "r"(tmem), "r"(ncols));
}
__device__ __forceinline__ void mbar_init(uint32_t mb, uint32_t cnt) {
    asm volatile("mbarrier.init.shared.b64 [%0], %1;" :: "r"(mb), "r"(cnt) : "memory");
}
__device__ __forceinline__ void mbar_wait(uint32_t mb, uint32_t parity) {
    asm volatile("{\n\t.reg .pred P;\n\t"
                 "WL_%=:\n\t"
                 "mbarrier.try_wait.parity.acquire.cta.shared::cta.b64 P, [%0], %1, 0x989680;\n\t"
                 "@!P bra WL_%=;\n\t}"
                 :: "r"(mb), "r"(parity) : "memory");
}
__device__ __forceinline__ void tc_commit(uint32_t mb) {
    asm volatile("tcgen05.commit.cta_group::1.mbarrier::arrive::one.shared::cluster.b64 [%0];"
                 :: "r"(mb) : "memory");
}
__device__ __forceinline__ void fence_async_smem() {
    asm volatile("fence.proxy.async.shared::cta;" ::: "memory");
}
__device__ __forceinline__ void tc_fence_after() {
    asm volatile("tcgen05.fence::after_thread_sync;" ::: "memory");
}
__device__ __forceinline__ void tc_wait_ld() {
    asm volatile("tcgen05.wait::ld.sync.aligned;" ::: "memory");
}
__device__ __forceinline__ void mma_ss(uint32_t d, uint64_t a, uint64_t b,
                                       uint32_t idesc, bool en) {
    uint32_t e = en ? 1u : 0u;
    asm volatile("{\n\t.reg .pred p;\n\tsetp.ne.u32 p, %4, 0;\n\t"
                 "tcgen05.mma.cta_group::1.kind::f16 [%0], %1, %2, %3, "
                 "{%5, %5, %5, %5}, p;\n\t}"
                 :: "r"(d), "l"(a), "l"(b), "r"(idesc), "r"(e), "r"(0u)
                 : "memory");
}
__device__ __forceinline__ void ldtm32(uint32_t* r, uint32_t tmem) {
    asm volatile(
        "tcgen05.ld.sync.aligned.32x32b.x32.b32 "
        "{%0, %1, %2, %3, %4, %5, %6, %7, %8, %9, %10, %11, %12, %13, %14, %15, "
        "%16, %17, %18, %19, %20, %21, %22, %23, %24, %25, %26, %27, %28, %29, %30, %31}, [%32];"
        : "=r"(r[0]), "=r"(r[1]), "=r"(r[2]), "=r"(r[3]),
          "=r"(r[4]), "=r"(r[5]), "=r"(r[6]), "=r"(r[7]),
          "=r"(r[8]), "=r"(r[9]), "=r"(r[10]), "=r"(r[11]),
          "=r"(r[12]), "=r"(r[13]), "=r"(r[14]), "=r"(r[15]),
          "=r"(r[16]), "=r"(r[17]), "=r"(r[18]), "=r"(r[19]),
          "=r"(r[20]), "=r"(r[21]), "=r"(r[22]), "=r"(r[23]),
          "=r"(r[24]), "=r"(r[25]), "=r"(r[26]), "=r"(r[27]),
          "=r"(r[28]), "=r"(r[29]), "=r"(r[30]), "=r"(r[31])
        : "r"(tmem));
}
__device__ __forceinline__ uint64_t mk_desc(uint32_t saddr) {
    const uint64_t base = (uint64_t(2) << 61) | (uint64_t(1) << 46)
                        | (uint64_t(64) << 32) | (uint64_t(1) << 16);
    return base | ((uint64_t)(saddr >> 4) & 0x3FFF);
}
#define IDESC_128 ((1u << 4) | (1u << 7) | (1u << 10) | (16u << 17) | (8u << 24))
#endif // HAS_TCGEN05

__device__ __forceinline__ void mma16816(float* d, uint32_t a0, uint32_t a1,
                                         uint32_t a2, uint32_t a3,
                                         uint32_t b0, uint32_t b1) {
    asm volatile(
        "mma.sync.aligned.m16n8k16.row.col.f32.bf16.bf16.f32 "
        "{%0,%1,%2,%3}, {%4,%5,%6,%7}, {%8,%9}, {%0,%1,%2,%3};"
        : "+f"(d[0]), "+f"(d[1]), "+f"(d[2]), "+f"(d[3])
        : "r"(a0), "r"(a1), "r"(a2), "r"(a3), "r"(b0), "r"(b1));
}

// ---------------------------------------------------------------------------
// bf16-split GEMM: compile-time template (NO runtime struct selection).
// OUTMODE: 0 = fp32, 1 = (relu?)+bf16 hi/lo, 2 = fused GRU-post (N=512)
// ---------------------------------------------------------------------------
#define STAGE_B(NT) (32768 + 2 * (NT) * 128)
#define SMEM_G(NT)  (1024 + 2 * STAGE_B(NT) + 1024)

template<int ACT, int OUTMODE, int NT>
__device__ __forceinline__ void epi_one(
    int row, int col, float v, int N,
    const float* __restrict__ bias,
    float* __restrict__ Cf, bf16* __restrict__ Ch, bf16* __restrict__ Cl,
    const float* __restrict__ Yg, const float* __restrict__ zg,
    const float* __restrict__ xg, float* __restrict__ outg,
    bf16* __restrict__ oh, bf16* __restrict__ ol)
{
    if (OUTMODE == 2) {
        float yv = Yg[(size_t)row * 1536 + 1024 + col];
        float hh = tanhf(yv + v);
        size_t e = (size_t)row * 512 + col;
        float zz = zg[e];
        float o = (1.0f - zz) * xg[e] + zz * hh;
        outg[e] = o;
        if (oh) split1(o, oh + e, ol + e);
    } else {
        if (bias) v += bias[col];
        if (ACT) v = fmaxf(v, 0.0f);
        size_t idx = (size_t)row * N + col;
        if (OUTMODE == 0) {
            Cf[idx] = v;
        } else {
            bf16 h = __float2bfloat16(v);
            Ch[idx] = h;
            Cl[idx] = __float2bfloat16(v - __bfloat162float(h));
        }
    }
}

template<int ACT, int OUTMODE, int NT>
__global__ __launch_bounds__(256)
void gemm_tc(const bf16* __restrict__ Ah, const bf16* __restrict__ Al,
             const bf16* __restrict__ Bh, const bf16* __restrict__ Bl,
             const float* __restrict__ bias,
             float* __restrict__ Cf, bf16* __restrict__ Ch, bf16* __restrict__ Cl,
             const float* __restrict__ Yg, const float* __restrict__ zg,
             const float* __restrict__ xg, float* __restrict__ outg,
             bf16* __restrict__ oh, bf16* __restrict__ ol,
             int M, int N, int K)
{
    extern __shared__ char dsm[];
    const uint32_t sraw = smem_u32(dsm);
    const uint32_t tile0 = (sraw + 1024u) & ~1023u;
    const uint32_t off0 = tile0 - sraw;
    const uint32_t STG = STAGE_B(NT);

    const int tid = threadIdx.x;
    const int wid = tid >> 5, lid = tid & 31;
    const int bm = blockIdx.y * 128;
    const int bn = blockIdx.x * NT;
    char* smc = dsm;
    const int nk = K >> 6;

#if HAS_TCGEN05
    const uint32_t mb0 = sraw + 8, mb1 = sraw + 16;

    if (wid == 0) { tc_alloc(sraw, (NT > 128) ? 256 : 128); tc_relinq(); }
    if (tid == 0) { mbar_init(mb0, 1); mbar_init(mb1, 1); }
    __syncthreads();
    uint32_t tmem;
    asm volatile("ld.shared.b32 %0, [%1];" : "=r"(tmem) : "r"(sraw));

    load_chunk_cp<NT>(tile0, Ah, Al, Bh, Bl, bm, bn, N, K, 0, tid);

    int ph0 = 0, ph1 = 0;
    for (int k = 0; k < nk; ++k) {
        const int s = k & 1;
        if (k + 1 < nk) {
            if (k >= 1) {
                if (((k + 1) & 1) == 0) { mbar_wait(mb0, ph0); ph0 ^= 1; }
                else                    { mbar_wait(mb1, ph1); ph1 ^= 1; }
            }
            load_chunk_cp<NT>(tile0 + ((k + 1) & 1) * STG,
                              Ah, Al, Bh, Bl, bm, bn, N, K, (k + 1) * 64, tid);
            asm volatile("cp.async.wait_group 1;" ::: "memory");
        } else {
            asm volatile("cp.async.wait_group 0;" ::: "memory");
        }
        fence_async_smem();
        __syncthreads();

        if (wid == 0) {
            if (elect1()) {
                uint32_t base = tile0 + s * STG;
                uint64_t dah = mk_desc(base);
                uint64_t dal = mk_desc(base + 16384);
                uint64_t dbh = mk_desc(base + 32768);
                uint64_t dbl = mk_desc(base + 32768 + NT * 128);
                #pragma unroll
                for (int ks = 0; ks < 4; ++ks) {
                    uint64_t o = (uint64_t)(ks * 2);
                    bool en0 = (k > 0) || (ks > 0);
                    mma_ss(tmem, dah + o, dbh + o, IDESC_128, en0);
                    mma_ss(tmem, dah + o, dbl + o, IDESC_128, true);
                    mma_ss(tmem, dal + o, dbh + o, IDESC_128, true);
                    if (NT > 128) {
                        mma_ss(tmem + 128, dah + o, dbh + 1024 + o, IDESC_128, en0);
                        mma_ss(tmem + 128, dah + o, dbl + 1024 + o, IDESC_128, true);
                        mma_ss(tmem + 128, dal + o, dbh + 1024 + o, IDESC_128, true);
                    }
                }
                tc_commit(s == 0 ? mb0 : mb1);
            }
        }
    }
    if (((nk - 1) & 1) == 0) mbar_wait(mb0, ph0);
    else                     mbar_wait(mb1, ph1);
    tc_fence_after();
    __syncthreads();

    float* sf = (float*)(smc + off0);
    #pragma unroll
    for (int nb = 0; nb < NT / 32; ++nb) {
        if (wid < 4) {
            uint32_t dr[32];
            ldtm32(dr, tmem + nb * 32);
            tc_wait_ld();
            int mrow = wid * 32 + lid;
            #pragma unroll
            for (int c = 0; c < 32; ++c) sf[mrow * 33 + c] = __uint_as_float(dr[c]);
        }
        __syncthreads();
        int cb = bn + nb * 32;
        if (cb < N) {
            int col = cb + lid;
            if (col < N) {
                int rbase = (tid >> 5) * 16;
                #pragma unroll
                for (int rr = 0; rr < 16; ++rr) {
                    int row = rbase + rr;
                    epi_one<ACT, OUTMODE, NT>(bm + row, col, sf[row * 33 + lid],
                                              N, bias, Cf, Ch, Cl,
                                              Yg, zg, xg, outg, oh, ol);
                }
            }
        }
        __syncthreads();
    }
    if (wid == 0) tc_dealloc(tmem, (NT > 128) ? 256 : 128);

#else  // ------------------- mma.sync fallback path -------------------------
    const int NTW = NT / 4;
    const int NNT = NT / 32;
    const int wm0 = (wid >> 2) * 64;
    const int wn0 = (wid & 3) * NTW;
    const int g = lid >> 2, tg = lid & 3;

    float acc[4][NT / 32][4];
    #pragma unroll
    for (int x = 0; x < 4; ++x)
        #pragma unroll
        for (int y = 0; y < NNT; ++y)
            #pragma unroll
            for (int c = 0; c < 4; ++c) acc[x][y][c] = 0.0f;

    load_chunk_cp<NT>(tile0, Ah, Al, Bh, Bl, bm, bn, N, K, 0, tid);

    for (int k = 0; k < nk; ++k) {
        const uint32_t oS = off0 + (uint32_t)(k & 1) * STG;
        if (k + 1 < nk) {
            load_chunk_cp<NT>(tile0 + ((k + 1) & 1) * STG,
                              Ah, Al, Bh, Bl, bm, bn, N, K, (k + 1) * 64, tid);
            asm volatile("cp.async.wait_group 1;" ::: "memory");
        } else {
            asm volatile("cp.async.wait_group 0;" ::: "memory");
        }
        __syncthreads();

        const uint32_t oA_h = oS, oA_l = oS + 16384;
        const uint32_t oB_h = oS + 32768, oB_l = oS + 32768 + NT * 128;

        #pragma unroll
        for (int ks = 0; ks < 4; ++ks) {
            const uint32_t kb = (uint32_t)(ks * 32 + tg * 4);
            uint32_t bh0[NT / 32], bh1[NT / 32], bl0[NT / 32], bl1[NT / 32];
            #pragma unroll
            for (int nt = 0; nt < NNT; ++nt) {
                uint32_t row = (uint32_t)(wn0 + nt * 8 + g);
                uint32_t o1 = row * 128 + kb;
                uint32_t o2 = o1 + 16;
                uint32_t s1 = o1 ^ ((o1 >> 3) & 0x70);
                uint32_t s2 = o2 ^ ((o2 >> 3) & 0x70);
                bh0[nt] = *(const uint32_t*)(smc + oB_h + s1);
                bh1[nt] = *(const uint32_t*)(smc + oB_h + s2);
                bl0[nt] = *(const uint32_t*)(smc + oB_l + s1);
                bl1[nt] = *(const uint32_t*)(smc + oB_l + s2);
            }
            #pragma unroll
            for (int mt = 0; mt < 4; ++mt) {
                uint32_t r0 = (uint32_t)(wm0 + mt * 16 + g);
                uint32_t o_r0c0 = r0 * 128 + kb;
                uint32_t o_r8c0 = o_r0c0 + 8 * 128;
                uint32_t o_r0c8 = o_r0c0 + 16;
                uint32_t o_r8c8 = o_r8c0 + 16;
                uint32_t s00 = o_r0c0 ^ ((o_r0c0 >> 3) & 0x70);
                uint32_t s80 = o_r8c0 ^ ((o_r8c0 >> 3) & 0x70);
                uint32_t s08 = o_r0c8 ^ ((o_r0c8 >> 3) & 0x70);
                uint32_t s88 = o_r8c8 ^ ((o_r8c8 >> 3) & 0x70);
                uint32_t ah0 = *(const uint32_t*)(smc + oA_h + s00);
                uint32_t ah1 = *(const uint32_t*)(smc + oA_h + s80);
                uint32_t ah2 = *(const uint32_t*)(smc + oA_h + s08);
                uint32_t ah3 = *(const uint32_t*)(smc + oA_h + s88);
                uint32_t al0 = *(const uint32_t*)(smc + oA_l + s00);
                uint32_t al1 = *(const uint32_t*)(smc + oA_l + s80);
                uint32_t al2 = *(const uint32_t*)(smc + oA_l + s08);
                uint32_t al3 = *(const uint32_t*)(smc + oA_l + s88);
                #pragma unroll
                for (int nt = 0; nt < NNT; ++nt) {
                    mma16816(acc[mt][nt], ah0, ah1, ah2, ah3, bh0[nt], bh1[nt]);
                    mma16816(acc[mt][nt], ah0, ah1, ah2, ah3, bl0[nt], bl1[nt]);
                    mma16816(acc[mt][nt], al0, al1, al2, al3, bh0[nt], bh1[nt]);
                }
            }
        }
        __syncthreads();
    }

    #pragma unroll
    for (int mt = 0; mt < 4; ++mt) {
        #pragma unroll
        for (int nt = 0; nt < NNT; ++nt) {
            int r0 = bm + wm0 + mt * 16 + g;
            int c0 = bn + wn0 + nt * 8 + tg * 2;
            #pragma unroll
            for (int half = 0; half < 2; ++half) {
                int row = r0 + half * 8;
                #pragma unroll
                for (int cc = 0; cc < 2; ++cc) {
                    int col = c0 + cc;
                    if (col < N)
                        epi_one<ACT, OUTMODE, NT>(row, col, acc[mt][nt][half*2+cc],
                                                  N, bias, Cf, Ch, Cl,
                                                  Yg, zg, xg, outg, oh, ol);
                }
            }
        }
    }
#endif
}

// ---------------------------------------------------------------------------
// Mega weight split
// ---------------------------------------------------------------------------
struct SArgs {
    const float4* s[8];
    uint2* h[8];
    uint2* l[8];
    int off[9];
};

__global__ __launch_bounds__(256)
void wsplit_all(SArgs a)
{
    int i = blockIdx.x * 256 + threadIdx.x;
    #pragma unroll
    for (int k = 0; k < 8; ++k) {
        if (i >= a.off[k] && i < a.off[k + 1]) {
            int j = i - a.off[k];
            pack4(a.s[k][j], a.h[k] + j, a.l[k] + j);
        }
    }
}

// ---------------------------------------------------------------------------
// LayerNorm (+ optional raw-input hi/lo split)
// ---------------------------------------------------------------------------
__global__ __launch_bounds__(256)
void ln_kernel(const float* __restrict__ x, const float* __restrict__ g,
               const float* __restrict__ b, bf16* __restrict__ yh,
               bf16* __restrict__ yl, bf16* __restrict__ rh,
               bf16* __restrict__ rl)
{
    __shared__ float rbuf[8];
    __shared__ float smean, srstd;
    const int row = blockIdx.x;
    const int tid = threadIdx.x;
    const int lane = tid & 31, warp = tid >> 5;
    const float* xr = x + (size_t)row * D_MODEL;

    float v0 = xr[tid], v1 = xr[tid + 256];
    size_t base = (size_t)row * D_MODEL;
    if (rh) {
        split1(v0, rh + base + tid,       rl + base + tid);
        split1(v1, rh + base + tid + 256, rl + base + tid + 256);
    }

    float s = v0 + v1;
    #pragma unroll
    for (int o = 16; o; o >>= 1) s += __shfl_down_sync(0xffffffffu, s, o);
    if (!lane) rbuf[warp] = s;
    __syncthreads();
    if (warp == 0) {
        float t = (lane < 8) ? rbuf[lane] : 0.0f;
        #pragma unroll
        for (int o = 4; o; o >>= 1) t += __shfl_down_sync(0xffffffffu, t, o);
        if (!lane) smean = t * (1.0f / D_MODEL);
    }
    __syncthreads();
    float m = smean;

    float d0 = v0 - m, d1 = v1 - m;
    float sv = d0 * d0 + d1 * d1;
    #pragma unroll
    for (int o = 16; o; o >>= 1) sv += __shfl_down_sync(0xffffffffu, sv, o);
    if (!lane) rbuf[warp] = sv;
    __syncthreads();
    if (warp == 0) {
        float t = (lane < 8) ? rbuf[lane] : 0.0f;
        #pragma unroll
        for (int o = 4; o; o >>= 1) t += __shfl_down_sync(0xffffffffu, t, o);
        if (!lane) srstd = rsqrtf(t * (1.0f / D_MODEL) + 1e-5f);
    }
    __syncthreads();
    float r = srstd;

    float o0 = d0 * r * g[tid]       + b[tid];
    float o1 = d1 * r * g[tid + 256] + b[tid + 256];
    split1(o0, yh + base + tid,       yl + base + tid);
    split1(o1, yh + base + tid + 256, yl + base + tid + 256);
}

// ---------------------------------------------------------------------------
// Fast scan: cp.async double-buffered prefetch, socc table, 2 barriers/step,
// V-state (R=8) in registers of threads 0..63.
// ---------------------------------------------------------------------------
__global__ __launch_bounds__(256)
void scan_kernel(const float* __restrict__ allproj, const int* __restrict__ terms,
                 const float* __restrict__ tick, const float* __restrict__ tk,
                 const float* __restrict__ tv, const float* __restrict__ s_prev,
                 bf16* __restrict__ core_h, bf16* __restrict__ core_l)
{
    const int bh = blockIdx.x;
    const int b = bh >> 3, h = bh & 7;
    const int tid = threadIdx.x;
    const int lane = tid & 31, warp = tid >> 5;

    __shared__ float socc[T_][8];               // 4 KB
    __shared__ __align__(16) float buf[2][336]; // kqv 0..319, p 320..331, term @332
    __shared__ float red[9 * 8];

    // occ table (once)
    const float tickb = tick[b];
    for (int i = tid; i < T_ * 8; i += 256) {
        int t = i >> 3, u = i & 7;
        float om = -3.14159265358979323846f
                 + (float)u * (6.28318530717958647692f / 7.0f);
        socc[t][u] = cosf((tickb + (float)(t + 1)) * om);
    }

    // states
    float Kst[8], S;
    #pragma unroll
    for (int r = 0; r < 8; ++r)
        Kst[r] = tk[(((size_t)b * R_ + r) * H_ + h) * 256 + tid];
    S = s_prev[((size_t)b * H_ + h) * 256 + tid];
    float Vst[8];
    if (tid < 64) {
        #pragma unroll
        for (int r = 0; r < 8; ++r)
            Vst[r] = tv[(((size_t)b * R_ + r) * H_ + h) * 64 + tid];
    }

    const uint32_t sb0 = smem_u32(&buf[0][0]);
    const int d = tid >> 2, j = tid & 3;

    // prefetch helper (inline lambda-style via macro)
    #define SCAN_PREFETCH(tt, sbuf) do {                                        \
        size_t rb_ = ((size_t)(tt) * B_ + b) * TOTAL_PROJ;                      \
        if (tid < 80)      cp16((sbuf) + tid * 16, allproj + rb_ + h * 320 + tid * 4); \
        else if (tid < 83) cp16((sbuf) + 1280 + (tid - 80) * 16,                \
                                allproj + rb_ + KQV_DIM + h * 12 + (tid - 80) * 4); \
        else if (tid == 83) cp4((sbuf) + 1328, terms + (tt) * B_ + b);          \
        cp_commit();                                                            \
    } while (0)

    SCAN_PREFETCH(0, sb0);
    __syncthreads();  // also covers socc table + initial loads ordering

    for (int t = 0; t < T_; ++t) {
        const float* cbuf = &buf[t & 1][0];
        if (t + 1 < T_) {
            SCAN_PREFETCH(t + 1, sb0 + ((t + 1) & 1) * 1344u);
            asm volatile("cp.async.wait_group 1;" ::: "memory");
        } else {
            asm volatile("cp.async.wait_group 0;" ::: "memory");
        }
        __syncthreads();   // buf[t&1] visible to all

        const float term = 1.0f - (float)(*(const int*)&cbuf[332]);
        const float* oc = socc[t];

        // --- K / S side ---
        float ke = fmaxf(cbuf[d], 0.0f)       * fmaxf(cbuf[320 + j], 0.0f);
        float qe = fmaxf(cbuf[64 + d], 0.0f)  * fmaxf(cbuf[324 + j], 0.0f);
        float ge = sigf(cbuf[256 + d])        * sigf(cbuf[328 + j]);
        float kg = ke * ge;
        float dg = (1.0f - ge) * term;
        S = fmaf(dg, S, kg);
        float loc[9];
        #pragma unroll
        for (int r = 0; r < 8; ++r) {
            Kst[r] = fmaf(dg, Kst[r], kg * oc[r]);
            loc[r] = Kst[r] * qe;
        }
        loc[8] = S * qe;

        // --- V side (reads cbuf BEFORE the barrier) ---
        if (tid < 64) {
            float bs = sigf(cbuf[192 + tid]);
            float vg = cbuf[128 + tid] * bs;
            float db = (1.0f - bs) * term;
            #pragma unroll
            for (int r = 0; r < 8; ++r)
                Vst[r] = fmaf(db, Vst[r], vg * oc[r]);
        }

        // --- 9 warp reductions ---
        #pragma unroll
        for (int v = 0; v < 9; ++v) {
            float x = loc[v];
            x += __shfl_down_sync(0xffffffffu, x, 16);
            x += __shfl_down_sync(0xffffffffu, x, 8);
            x += __shfl_down_sync(0xffffffffu, x, 4);
            x += __shfl_down_sync(0xffffffffu, x, 2);
            x += __shfl_down_sync(0xffffffffu, x, 1);
            if (lane == 0) red[v * 8 + warp] = x;
        }
        __syncthreads();   // red visible; also guards buf reuse

        if (tid < 64) {
            float kdq[9];
            #pragma unroll
            for (int v = 0; v < 9; ++v) {
                float s = red[v * 8 + 0] + red[v * 8 + 1] + red[v * 8 + 2]
                        + red[v * 8 + 3] + red[v * 8 + 4] + red[v * 8 + 5]
                        + red[v * 8 + 6] + red[v * 8 + 7];
                kdq[v] = s;
            }
            float kv = 0.0f;
            #pragma unroll
            for (int r = 0; r < 8; ++r) kv = fmaf(Vst[r], kdq[r], kv);
            float val = kv / (16.0f * (kdq[8] + 1e-6f));
            size_t idx = ((size_t)t * B_ + b) * D_MODEL + h * 64 + tid;
            split1(val, core_h + idx, core_l + idx);
        }
    }
    #undef SCAN_PREFETCH
}

// ---------------------------------------------------------------------------
// GRU stage 1 (vectorized)
// ---------------------------------------------------------------------------
__global__ __launch_bounds__(256)
void gru_pre(const float4* __restrict__ x, const float* __restrict__ Y3,
             const float* __restrict__ X2, uint2* __restrict__ rxh,
             uint2* __restrict__ rxl, float4* __restrict__ z, int n4)
{
    int i = blockIdx.x * 256 + threadIdx.x;
    if (i >= n4) return;
    int row = i >> 7, c = (i & 127) * 4;
    const float4 y0 = *(const float4*)&Y3[(size_t)row * 1536 + c];
    const float4 y1 = *(const float4*)&Y3[(size_t)row * 1536 + 512 + c];
    const float4 x0 = *(const float4*)&X2[(size_t)row * 1024 + c];
    const float4 x1 = *(const float4*)&X2[(size_t)row * 1024 + 512 + c];
    float4 xv = x[i];
    float4 zz;
    zz.x = sigf(y1.x + x1.x - 2.0f);
    zz.y = sigf(y1.y + x1.y - 2.0f);
    zz.z = sigf(y1.z + x1.z - 2.0f);
    zz.w = sigf(y1.w + x1.w - 2.0f);
    float4 rx;
    rx.x = sigf(y0.x + x0.x) * xv.x;
    rx.y = sigf(y0.y + x0.y) * xv.y;
    rx.z = sigf(y0.z + x0.z) * xv.z;
    rx.w = sigf(y0.w + x0.w) * xv.w;
    z[i] = zz;
    pack4(rx, rxh + i, rxl + i);
}

// ---------------------------------------------------------------------------
// Launch
// ---------------------------------------------------------------------------
template<typename Tp>
static Tp* symptr(const void* sym) {
    void* p = nullptr;
    cudaGetSymbolAddress(&p, sym);
    return (Tp*)p;
}

extern "C" void kernel_launch(void* const* d_in, const int* in_sizes, int n_in,
                              void* d_out, int out_size)
{
    const float* inputs   = (const float*)d_in[0];
    const int*   terms    = (const int*)  d_in[1];
    const float* tilde_k  = (const float*)d_in[2];
    const float* tilde_v  = (const float*)d_in[3];
    const float* s_prev   = (const float*)d_in[4];
    const float* tick     = (const float*)d_in[5];
    const float* w_proj   = (const float*)d_in[6];
    const float* b_proj   = (const float*)d_in[7];
    const float* w_attn   = (const float*)d_in[8];
    const float* b_attn   = (const float*)d_in[9];
    const float* ln1_g    = (const float*)d_in[10];
    const float* ln1_b    = (const float*)d_in[11];
    const float* ln2_g    = (const float*)d_in[12];
    const float* ln2_b    = (const float*)d_in[13];
    const float* gru1_w   = (const float*)d_in[14];
    const float* gru1_u   = (const float*)d_in[15];
    const float* gru2_w   = (const float*)d_in[16];
    const float* gru2_u   = (const float*)d_in[17];
    const float* ffc_w1   = (const float*)d_in[18];
    const float* ffc_b1   = (const float*)d_in[19];
    const float* ffc_w2   = (const float*)d_in[20];
    const float* ffc_b2   = (const float*)d_in[21];
    float* out = (float*)d_out;

    float* allproj = symptr<float>(g_allproj);
    float* Y3   = symptr<float>(g_Y3);
    float* X2   = symptr<float>(g_X2);
    float* zb   = symptr<float>(g_zb);
    float* gate1= symptr<float>(g_gate1);

    bf16 *in_h = symptr<bf16>(g_in_h),  *in_l = symptr<bf16>(g_in_l);
    bf16 *xn_h = symptr<bf16>(g_xn_h),  *xn_l = symptr<bf16>(g_xn_l);
    bf16 *co_h = symptr<bf16>(g_core_h),*co_l = symptr<bf16>(g_core_l);
    bf16 *ar_h = symptr<bf16>(g_arelu_h),*ar_l= symptr<bf16>(g_arelu_l);
    bf16 *rx_h = symptr<bf16>(g_rx_h),  *rx_l = symptr<bf16>(g_rx_l);
    bf16 *g1_h = symptr<bf16>(g_g1_h),  *g1_l = symptr<bf16>(g_g1_l);
    bf16 *ff_h = symptr<bf16>(g_ff_h),  *ff_l = symptr<bf16>(g_ff_l);
    bf16 *hd_h = symptr<bf16>(g_hid_h), *hd_l = symptr<bf16>(g_hid_l);

    bf16 *wp_h = symptr<bf16>(g_wproj_h), *wp_l = symptr<bf16>(g_wproj_l);
    bf16 *wa_h = symptr<bf16>(g_wattn_h), *wa_l = symptr<bf16>(g_wattn_l);
    bf16 *w1w_h= symptr<bf16>(g_g1w_h),   *w1w_l= symptr<bf16>(g_g1w_l);
    bf16 *w1u_h= symptr<bf16>(g_g1u_h),   *w1u_l= symptr<bf16>(g_g1u_l);
    bf16 *w2w_h= symptr<bf16>(g_g2w_h),   *w2w_l= symptr<bf16>(g_g2w_l);
    bf16 *w2u_h= symptr<bf16>(g_g2u_h),   *w2u_l= symptr<bf16>(g_g2u_l);
    bf16 *f1_h = symptr<bf16>(g_fw1_h),   *f1_l = symptr<bf16>(g_fw1_l);
    bf16 *f2_h = symptr<bf16>(g_fw2_h),   *f2_l = symptr<bf16>(g_fw2_l);

    cudaFuncSetAttribute(gemm_tc<0,0,128>, cudaFuncAttributeMaxDynamicSharedMemorySize, SMEM_G(128));
    cudaFuncSetAttribute(gemm_tc<1,1,128>, cudaFuncAttributeMaxDynamicSharedMemorySize, SMEM_G(128));
    cudaFuncSetAttribute(gemm_tc<0,2,128>, cudaFuncAttributeMaxDynamicSharedMemorySize, SMEM_G(128));
    cudaFuncSetAttribute(gemm_tc<0,0,256>, cudaFuncAttributeMaxDynamicSharedMemorySize, SMEM_G(256));
    cudaFuncSetAttribute(gemm_tc<1,1,256>, cudaFuncAttributeMaxDynamicSharedMemorySize, SMEM_G(256));

    const int n = NTOK * D_MODEL;
    const int n4 = n / 4;
    dim3 thr(256);
    const int eg4 = (n4 + 255) / 256;
    const int OFF2 = 2 * D_MODEL * D_MODEL;

    // 1) ln1 + raw input split
    ln_kernel<<<NTOK, thr>>>(inputs, ln1_g, ln1_b, xn_h, xn_l, in_h, in_l);

    // 2) mega weight split
    {
        SArgs sa;
        const float* srcs[8] = {w_proj, w_attn, gru1_w, gru1_u,
                                gru2_w, gru2_u, ffc_w1, ffc_w2};
        bf16* hs[8] = {wp_h, wa_h, w1w_h, w1u_h, w2w_h, w2u_h, f1_h, f2_h};
        bf16* ls[8] = {wp_l, wa_l, w1w_l, w1u_l, w2w_l, w2u_l, f1_l, f2_l};
        int cnts[8] = {WPROJ_N, WATTN_N, WGRU_N, WGRU_N,
                       WGRU_N, WGRU_N, WFFC1_N, WFFC2_N};
        int acc = 0;
        for (int k = 0; k < 8; ++k) {
            sa.s[k] = (const float4*)srcs[k];
            sa.h[k] = (uint2*)hs[k];
            sa.l[k] = (uint2*)ls[k];
            sa.off[k] = acc;
            acc += cnts[k] / 4;
        }
        sa.off[8] = acc;
        wsplit_all<<<(acc + 255) / 256, thr>>>(sa);
    }

    // 3) proj GEMM (NT=256)
    gemm_tc<0,0,256><<<dim3((TOTAL_PROJ + 255) / 256, 32), thr, SMEM_G(256)>>>(
        xn_h, xn_l, wp_h, wp_l, b_proj, allproj, nullptr, nullptr,
        nullptr, nullptr, nullptr, nullptr, nullptr, nullptr,
        NTOK, TOTAL_PROJ, D_MODEL);

    // 4) scan (fast)
    scan_kernel<<<B_ * H_, thr>>>(allproj, terms, tick, tilde_k, tilde_v,
                                  s_prev, co_h, co_l);

    // 5) attn (relu, hi/lo)
    gemm_tc<1,1,128><<<dim3(4, 32), thr, SMEM_G(128)>>>(
        co_h, co_l, wa_h, wa_l, b_attn, nullptr, ar_h, ar_l,
        nullptr, nullptr, nullptr, nullptr, nullptr, nullptr,
        NTOK, D_MODEL, D_MODEL);

    // 6) GRU1 Y3
    gemm_tc<0,0,256><<<dim3(6, 32), thr, SMEM_G(256)>>>(
        ar_h, ar_l, w1w_h, w1w_l, nullptr, Y3, nullptr, nullptr,
        nullptr, nullptr, nullptr, nullptr, nullptr, nullptr,
        NTOK, 3 * D_MODEL, D_MODEL);

    // 7) GRU1 X2
    gemm_tc<0,0,256><<<dim3(4, 32), thr, SMEM_G(256)>>>(
        in_h, in_l, w1u_h, w1u_l, nullptr, X2, nullptr, nullptr,
        nullptr, nullptr, nullptr, nullptr, nullptr, nullptr,
        NTOK, 2 * D_MODEL, D_MODEL);

    // 8) gru_pre 1
    gru_pre<<<eg4, thr>>>((const float4*)inputs, Y3, X2,
                          (uint2*)rx_h, (uint2*)rx_l, (float4*)zb, n4);

    // 9) RX GEMM + fused gru_post -> gate1 (+hi/lo)
    gemm_tc<0,2,128><<<dim3(4, 32), thr, SMEM_G(128)>>>(
        rx_h, rx_l, w1u_h + OFF2, w1u_l + OFF2, nullptr, nullptr, nullptr, nullptr,
        Y3, zb, inputs, gate1, g1_h, g1_l,
        NTOK, D_MODEL, D_MODEL);

    // 10) ln2
    ln_kernel<<<NTOK, thr>>>(gate1, ln2_g, ln2_b, xn_h, xn_l, nullptr, nullptr);

    // 11) FFC1 (relu, hi/lo)
    gemm_tc<1,1,256><<<dim3(8, 32), thr, SMEM_G(256)>>>(
        xn_h, xn_l, f1_h, f1_l, ffc_b1, nullptr, hd_h, hd_l,
        nullptr, nullptr, nullptr, nullptr, nullptr, nullptr,
        NTOK, D_FFC, D_MODEL);

    // 12) FFC2 (relu, hi/lo)
    gemm_tc<1,1,128><<<dim3(4, 32), thr, SMEM_G(128)>>>(
        hd_h, hd_l, f2_h, f2_l, ffc_b2, nullptr, ff_h, ff_l,
        nullptr, nullptr, nullptr, nullptr, nullptr, nullptr,
        NTOK, D_MODEL, D_FFC);

    // 13) GRU2 Y3
    gemm_tc<0,0,256><<<dim3(6, 32), thr, SMEM_G(256)>>>(
        ff_h, ff_l, w2w_h, w2w_l, nullptr, Y3, nullptr, nullptr,
        nullptr, nullptr, nullptr, nullptr, nullptr, nullptr,
        NTOK, 3 * D_MODEL, D_MODEL);

    // 14) GRU2 X2
    gemm_tc<0,0,256><<<dim3(4, 32), thr, SMEM_G(256)>>>(
        g1_h, g1_l, w2u_h, w2u_l, nullptr, X2, nullptr, nullptr,
        nullptr, nullptr, nullptr, nullptr, nullptr, nullptr,
        NTOK, 2 * D_MODEL, D_MODEL);

    // 15) gru_pre 2
    gru_pre<<<eg4, thr>>>((const float4*)gate1, Y3, X2,
                          (uint2*)rx_h, (uint2*)rx_l, (float4*)zb, n4);

    // 16) RX GEMM + fused gru_post -> out
    gemm_tc<0,2,128><<<dim3(4, 32), thr, SMEM_G(128)>>>(
        rx_h, rx_l, w2u_h + OFF2, w2u_l + OFF2, nullptr, nullptr, nullptr, nullptr,
        Y3, zb, gate1, out, nullptr, nullptr,
        NTOK, D_MODEL, D_MODEL);
}

// round 13
// speedup vs baseline: 1.8872x; 1.0414x over previous
#include <cuda_runtime.h>
#include <cuda_bf16.h>
#include <math.h>
#include <stdint.h>

// Problem constants
#define D_MODEL 512
#define H_ 8
#define HD_ 64
#define ETA_ 4
#define R_ 8
#define D_FFC 2048
#define T_ 128
#define B_ 32
#define NTOK (T_*B_)            // 4096
#define TOTAL_PROJ 2656
#define KQV_DIM 2560

typedef __nv_bfloat16 bf16;

#if defined(__CUDA_ARCH_FEAT_SM103_ALL) || defined(__CUDA_ARCH_FEAT_SM100_ALL)
#define HAS_TCGEN05 1
#else
#define HAS_TCGEN05 0
#endif

// ---------------------------------------------------------------------------
// Scratch
// ---------------------------------------------------------------------------
__device__ float g_allproj[NTOK * TOTAL_PROJ];
__device__ float g_Y3   [NTOK * 3 * D_MODEL];
__device__ float g_X2   [NTOK * 2 * D_MODEL];
__device__ float g_zb   [NTOK * D_MODEL];
__device__ float g_gate1[NTOK * D_MODEL];

__device__ __align__(256) bf16 g_in_h   [NTOK * D_MODEL], g_in_l   [NTOK * D_MODEL];
__device__ __align__(256) bf16 g_xn_h   [NTOK * D_MODEL], g_xn_l   [NTOK * D_MODEL];
__device__ __align__(256) bf16 g_core_h [NTOK * D_MODEL], g_core_l [NTOK * D_MODEL];
__device__ __align__(256) bf16 g_arelu_h[NTOK * D_MODEL], g_arelu_l[NTOK * D_MODEL];
__device__ __align__(256) bf16 g_rx_h   [NTOK * D_MODEL], g_rx_l   [NTOK * D_MODEL];
__device__ __align__(256) bf16 g_g1_h   [NTOK * D_MODEL], g_g1_l   [NTOK * D_MODEL];
__device__ __align__(256) bf16 g_ff_h   [NTOK * D_MODEL], g_ff_l   [NTOK * D_MODEL];
__device__ __align__(256) bf16 g_hid_h  [NTOK * D_FFC],   g_hid_l  [NTOK * D_FFC];

#define WPROJ_N (TOTAL_PROJ * D_MODEL)
#define WATTN_N (D_MODEL * D_MODEL)
#define WGRU_N  (3 * D_MODEL * D_MODEL)
#define WFFC1_N (D_FFC * D_MODEL)
#define WFFC2_N (D_MODEL * D_FFC)
__device__ __align__(256) bf16 g_wproj_h[WPROJ_N], g_wproj_l[WPROJ_N];
__device__ __align__(256) bf16 g_wattn_h[WATTN_N], g_wattn_l[WATTN_N];
__device__ __align__(256) bf16 g_g1w_h[WGRU_N], g_g1w_l[WGRU_N];
__device__ __align__(256) bf16 g_g1u_h[WGRU_N], g_g1u_l[WGRU_N];
__device__ __align__(256) bf16 g_g2w_h[WGRU_N], g_g2w_l[WGRU_N];
__device__ __align__(256) bf16 g_g2u_h[WGRU_N], g_g2u_l[WGRU_N];
__device__ __align__(256) bf16 g_fw1_h[WFFC1_N], g_fw1_l[WFFC1_N];
__device__ __align__(256) bf16 g_fw2_h[WFFC2_N], g_fw2_l[WFFC2_N];

// ---------------------------------------------------------------------------
// Fast math helpers (error ~1e-6 relative; rel_err budget is 1e-3)
// ---------------------------------------------------------------------------
__device__ __forceinline__ float frcp_fast(float x) {
    float r;
    asm("rcp.approx.f32 %0, %1;" : "=f"(r) : "f"(x));
    return r;
}
__device__ __forceinline__ float sigf(float x) {
    return frcp_fast(1.0f + __expf(-x));        // sat: x<<0 -> 1/inf -> 0
}
__device__ __forceinline__ float tanh_fast(float x) {
    // tanh(x) = 1 - 2/(e^{2x}+1); saturates to +/-1 correctly
    return 1.0f - 2.0f * frcp_fast(__expf(2.0f * x) + 1.0f);
}

__device__ __forceinline__ void split1(float v, bf16* h, bf16* l) {
    bf16 hv = __float2bfloat16(v);
    *h = hv;
    *l = __float2bfloat16(v - __bfloat162float(hv));
}

__device__ __forceinline__ void pack4(float4 v, uint2* hp, uint2* lp) {
    bf16 h0 = __float2bfloat16(v.x), h1 = __float2bfloat16(v.y);
    bf16 h2 = __float2bfloat16(v.z), h3 = __float2bfloat16(v.w);
    bf16 l0 = __float2bfloat16(v.x - __bfloat162float(h0));
    bf16 l1 = __float2bfloat16(v.y - __bfloat162float(h1));
    bf16 l2 = __float2bfloat16(v.z - __bfloat162float(h2));
    bf16 l3 = __float2bfloat16(v.w - __bfloat162float(h3));
    __nv_bfloat162 ha = __halves2bfloat162(h0, h1), hb = __halves2bfloat162(h2, h3);
    __nv_bfloat162 la = __halves2bfloat162(l0, l1), lb = __halves2bfloat162(l2, l3);
    uint2 hh, ll;
    hh.x = *reinterpret_cast<uint32_t*>(&ha);
    hh.y = *reinterpret_cast<uint32_t*>(&hb);
    ll.x = *reinterpret_cast<uint32_t*>(&la);
    ll.y = *reinterpret_cast<uint32_t*>(&lb);
    *hp = hh;
    *lp = ll;
}

__device__ __forceinline__ uint32_t smem_u32(const void* p) {
    uint32_t a;
    asm("{ .reg .u64 t; cvta.to.shared.u64 t, %1; cvt.u32.u64 %0, t; }"
        : "=r"(a) : "l"(p));
    return a;
}

__device__ __forceinline__ void cp16(uint32_t dst, const void* src) {
    asm volatile("cp.async.cg.shared.global [%0], [%1], 16;"
                 :: "r"(dst), "l"(src));
}
__device__ __forceinline__ void cp16z(uint32_t dst, const void* src, int sz) {
    asm volatile("cp.async.cg.shared.global [%0], [%1], 16, %2;"
                 :: "r"(dst), "l"(src), "r"(sz));
}
__device__ __forceinline__ void cp4(uint32_t dst, const void* src) {
    asm volatile("cp.async.ca.shared.global [%0], [%1], 4;"
                 :: "r"(dst), "l"(src));
}
__device__ __forceinline__ void cp_commit() {
    asm volatile("cp.async.commit_group;" ::: "memory");
}

// Warp sum (valid in lane 0)
__device__ __forceinline__ float warp_sum(float x) {
    x += __shfl_down_sync(0xffffffffu, x, 16);
    x += __shfl_down_sync(0xffffffffu, x, 8);
    x += __shfl_down_sync(0xffffffffu, x, 4);
    x += __shfl_down_sync(0xffffffffu, x, 2);
    x += __shfl_down_sync(0xffffffffu, x, 1);
    return x;
}

template<int NT>
__device__ __forceinline__ void load_chunk_cp(
    uint32_t sb, const bf16* Ah, const bf16* Al,
    const bf16* Bh, const bf16* Bl,
    int bm, int bn, int N, int K, int k0, int tid)
{
    #pragma unroll
    for (int p = 0; p < 4; ++p) {
        int id = tid + p * 256;
        int row = id >> 3, grp = id & 7;
        uint32_t boff = (uint32_t)(row * 128 + grp * 16);
        uint32_t sw = boff ^ ((boff >> 3) & 0x70);
        size_t ao = (size_t)(bm + row) * K + k0 + grp * 8;
        cp16(sb + sw,         Ah + ao);
        cp16(sb + 16384 + sw, Al + ao);
    }
    const uint32_t bBh = sb + 32768;
    const uint32_t bBl = sb + 32768 + NT * 128;
    #pragma unroll
    for (int p = 0; p < NT / 32; ++p) {
        int id = tid + p * 256;
        int row = id >> 3, grp = id & 7;
        uint32_t boff = (uint32_t)(row * 128 + grp * 16);
        uint32_t sw = boff ^ ((boff >> 3) & 0x70);
        int brow = bn + row;
        int ok = (brow < N) ? 16 : 0;
        size_t bo = (size_t)(brow < N ? brow : 0) * K + k0 + grp * 8;
        cp16z(bBh + sw, Bh + bo, ok);
        cp16z(bBl + sw, Bl + bo, ok);
    }
    cp_commit();
}

#if HAS_TCGEN05
__device__ __forceinline__ uint32_t elect1() {
    uint32_t r;
    asm volatile("{\n\t.reg .pred p;\n\telect.sync _|p, 0xFFFFFFFF;\n\t"
                 "selp.b32 %0,1,0,p;\n\t}" : "=r"(r));
    return r;
}
__device__ __forceinline__ void tc_alloc(uint32_t saddr, uint32_t ncols) {
    asm volatile("tcgen05.alloc.cta_group::1.sync.aligned.shared::cta.b32 [%0], %1;"
                 :: "r"(saddr), "r"(ncols) : "memory");
}
__device__ __forceinline__ void tc_relinq() {
    asm volatile("tcgen05.relinquish_alloc_permit.cta_group::1.sync.aligned;");
}
__device__ __forceinline__ void tc_dealloc(uint32_t tmem, uint32_t ncols) {
    asm volatile("tcgen05.dealloc.cta_group::1.sync.aligned.b32 %0, %1;"
                 :: "r"(tmem), "r"(ncols));
}
__device__ __forceinline__ void mbar_init(uint32_t mb, uint32_t cnt) {
    asm volatile("mbarrier.init.shared.b64 [%0], %1;" :: "r"(mb), "r"(cnt) : "memory");
}
__device__ __forceinline__ void mbar_wait(uint32_t mb, uint32_t parity) {
    asm volatile("{\n\t.reg .pred P;\n\t"
                 "WL_%=:\n\t"
                 "mbarrier.try_wait.parity.acquire.cta.shared::cta.b64 P, [%0], %1, 0x989680;\n\t"
                 "@!P bra WL_%=;\n\t}"
                 :: "r"(mb), "r"(parity) : "memory");
}
__device__ __forceinline__ void tc_commit(uint32_t mb) {
    asm volatile("tcgen05.commit.cta_group::1.mbarrier::arrive::one.shared::cluster.b64 [%0];"
                 :: "r"(mb) : "memory");
}
__device__ __forceinline__ void fence_async_smem() {
    asm volatile("fence.proxy.async.shared::cta;" ::: "memory");
}
__device__ __forceinline__ void tc_fence_after() {
    asm volatile("tcgen05.fence::after_thread_sync;" ::: "memory");
}
__device__ __forceinline__ void tc_wait_ld() {
    asm volatile("tcgen05.wait::ld.sync.aligned;" ::: "memory");
}
__device__ __forceinline__ void mma_ss(uint32_t d, uint64_t a, uint64_t b,
                                       uint32_t idesc, bool en) {
    uint32_t e = en ? 1u : 0u;
    asm volatile("{\n\t.reg .pred p;\n\tsetp.ne.u32 p, %4, 0;\n\t"
                 "tcgen05.mma.cta_group::1.kind::f16 [%0], %1, %2, %3, "
                 "{%5, %5, %5, %5}, p;\n\t}"
                 :: "r"(d), "l"(a), "l"(b), "r"(idesc), "r"(e), "r"(0u)
                 : "memory");
}
__device__ __forceinline__ void ldtm32(uint32_t* r, uint32_t tmem) {
    asm volatile(
        "tcgen05.ld.sync.aligned.32x32b.x32.b32 "
        "{%0, %1, %2, %3, %4, %5, %6, %7, %8, %9, %10, %11, %12, %13, %14, %15, "
        "%16, %17, %18, %19, %20, %21, %22, %23, %24, %25, %26, %27, %28, %29, %30, %31}, [%32];"
        : "=r"(r[0]), "=r"(r[1]), "=r"(r[2]), "=r"(r[3]),
          "=r"(r[4]), "=r"(r[5]), "=r"(r[6]), "=r"(r[7]),
          "=r"(r[8]), "=r"(r[9]), "=r"(r[10]), "=r"(r[11]),
          "=r"(r[12]), "=r"(r[13]), "=r"(r[14]), "=r"(r[15]),
          "=r"(r[16]), "=r"(r[17]), "=r"(r[18]), "=r"(r[19]),
          "=r"(r[20]), "=r"(r[21]), "=r"(r[22]), "=r"(r[23]),
          "=r"(r[24]), "=r"(r[25]), "=r"(r[26]), "=r"(r[27]),
          "=r"(r[28]), "=r"(r[29]), "=r"(r[30]), "=r"(r[31])
        : "r"(tmem));
}
__device__ __forceinline__ uint64_t mk_desc(uint32_t saddr) {
    const uint64_t base = (uint64_t(2) << 61) | (uint64_t(1) << 46)
                        | (uint64_t(64) << 32) | (uint64_t(1) << 16);
    return base | ((uint64_t)(saddr >> 4) & 0x3FFF);
}
#define IDESC_128 ((1u << 4) | (1u << 7) | (1u << 10) | (16u << 17) | (8u << 24))
#endif // HAS_TCGEN05

__device__ __forceinline__ void mma16816(float* d, uint32_t a0, uint32_t a1,
                                         uint32_t a2, uint32_t a3,
                                         uint32_t b0, uint32_t b1) {
    asm volatile(
        "mma.sync.aligned.m16n8k16.row.col.f32.bf16.bf16.f32 "
        "{%0,%1,%2,%3}, {%4,%5,%6,%7}, {%8,%9}, {%0,%1,%2,%3};"
        : "+f"(d[0]), "+f"(d[1]), "+f"(d[2]), "+f"(d[3])
        : "r"(a0), "r"(a1), "r"(a2), "r"(a3), "r"(b0), "r"(b1));
}

// ---------------------------------------------------------------------------
// bf16-split GEMM: compile-time template.
// OUTMODE: 0 = fp32, 1 = (relu?)+bf16 hi/lo, 2 = fused GRU-post (N=512)
// ---------------------------------------------------------------------------
#define STAGE_B(NT) (32768 + 2 * (NT) * 128)
#define SMEM_G(NT)  (1024 + 2 * STAGE_B(NT) + 1024)

template<int ACT, int OUTMODE, int NT>
__device__ __forceinline__ void epi_one(
    int row, int col, float v, int N,
    const float* __restrict__ bias,
    float* __restrict__ Cf, bf16* __restrict__ Ch, bf16* __restrict__ Cl,
    const float* __restrict__ Yg, const float* __restrict__ zg,
    const float* __restrict__ xg, float* __restrict__ outg,
    bf16* __restrict__ oh, bf16* __restrict__ ol)
{
    if (OUTMODE == 2) {
        float yv = Yg[(size_t)row * 1536 + 1024 + col];
        float hh = tanh_fast(yv + v);
        size_t e = (size_t)row * 512 + col;
        float zz = zg[e];
        float o = (1.0f - zz) * xg[e] + zz * hh;
        outg[e] = o;
        if (oh) split1(o, oh + e, ol + e);
    } else {
        if (bias) v += bias[col];
        if (ACT) v = fmaxf(v, 0.0f);
        size_t idx = (size_t)row * N + col;
        if (OUTMODE == 0) {
            Cf[idx] = v;
        } else {
            bf16 h = __float2bfloat16(v);
            Ch[idx] = h;
            Cl[idx] = __float2bfloat16(v - __bfloat162float(h));
        }
    }
}

template<int ACT, int OUTMODE, int NT>
__global__ __launch_bounds__(256)
void gemm_tc(const bf16* __restrict__ Ah, const bf16* __restrict__ Al,
             const bf16* __restrict__ Bh, const bf16* __restrict__ Bl,
             const float* __restrict__ bias,
             float* __restrict__ Cf, bf16* __restrict__ Ch, bf16* __restrict__ Cl,
             const float* __restrict__ Yg, const float* __restrict__ zg,
             const float* __restrict__ xg, float* __restrict__ outg,
             bf16* __restrict__ oh, bf16* __restrict__ ol,
             int M, int N, int K)
{
    extern __shared__ char dsm[];
    const uint32_t sraw = smem_u32(dsm);
    const uint32_t tile0 = (sraw + 1024u) & ~1023u;
    const uint32_t off0 = tile0 - sraw;
    const uint32_t STG = STAGE_B(NT);

    const int tid = threadIdx.x;
    const int wid = tid >> 5, lid = tid & 31;
    const int bm = blockIdx.y * 128;
    const int bn = blockIdx.x * NT;
    char* smc = dsm;
    const int nk = K >> 6;

#if HAS_TCGEN05
    const uint32_t mb0 = sraw + 8, mb1 = sraw + 16;

    if (wid == 0) { tc_alloc(sraw, (NT > 128) ? 256 : 128); tc_relinq(); }
    if (tid == 0) { mbar_init(mb0, 1); mbar_init(mb1, 1); }
    __syncthreads();
    uint32_t tmem;
    asm volatile("ld.shared.b32 %0, [%1];" : "=r"(tmem) : "r"(sraw));

    load_chunk_cp<NT>(tile0, Ah, Al, Bh, Bl, bm, bn, N, K, 0, tid);

    int ph0 = 0, ph1 = 0;
    for (int k = 0; k < nk; ++k) {
        const int s = k & 1;
        if (k + 1 < nk) {
            if (k >= 1) {
                if (((k + 1) & 1) == 0) { mbar_wait(mb0, ph0); ph0 ^= 1; }
                else                    { mbar_wait(mb1, ph1); ph1 ^= 1; }
            }
            load_chunk_cp<NT>(tile0 + ((k + 1) & 1) * STG,
                              Ah, Al, Bh, Bl, bm, bn, N, K, (k + 1) * 64, tid);
            asm volatile("cp.async.wait_group 1;" ::: "memory");
        } else {
            asm volatile("cp.async.wait_group 0;" ::: "memory");
        }
        fence_async_smem();
        __syncthreads();

        if (wid == 0) {
            if (elect1()) {
                uint32_t base = tile0 + s * STG;
                uint64_t dah = mk_desc(base);
                uint64_t dal = mk_desc(base + 16384);
                uint64_t dbh = mk_desc(base + 32768);
                uint64_t dbl = mk_desc(base + 32768 + NT * 128);
                #pragma unroll
                for (int ks = 0; ks < 4; ++ks) {
                    uint64_t o = (uint64_t)(ks * 2);
                    bool en0 = (k > 0) || (ks > 0);
                    mma_ss(tmem, dah + o, dbh + o, IDESC_128, en0);
                    mma_ss(tmem, dah + o, dbl + o, IDESC_128, true);
                    mma_ss(tmem, dal + o, dbh + o, IDESC_128, true);
                    if (NT > 128) {
                        mma_ss(tmem + 128, dah + o, dbh + 1024 + o, IDESC_128, en0);
                        mma_ss(tmem + 128, dah + o, dbl + 1024 + o, IDESC_128, true);
                        mma_ss(tmem + 128, dal + o, dbh + 1024 + o, IDESC_128, true);
                    }
                }
                tc_commit(s == 0 ? mb0 : mb1);
            }
        }
    }
    if (((nk - 1) & 1) == 0) mbar_wait(mb0, ph0);
    else                     mbar_wait(mb1, ph1);
    tc_fence_after();
    __syncthreads();

    float* sf = (float*)(smc + off0);
    #pragma unroll
    for (int nb = 0; nb < NT / 32; ++nb) {
        if (wid < 4) {
            uint32_t dr[32];
            ldtm32(dr, tmem + nb * 32);
            tc_wait_ld();
            int mrow = wid * 32 + lid;
            #pragma unroll
            for (int c = 0; c < 32; ++c) sf[mrow * 33 + c] = __uint_as_float(dr[c]);
        }
        __syncthreads();
        int cb = bn + nb * 32;
        if (cb < N) {
            int col = cb + lid;
            if (col < N) {
                int rbase = (tid >> 5) * 16;
                #pragma unroll
                for (int rr = 0; rr < 16; ++rr) {
                    int row = rbase + rr;
                    epi_one<ACT, OUTMODE, NT>(bm + row, col, sf[row * 33 + lid],
                                              N, bias, Cf, Ch, Cl,
                                              Yg, zg, xg, outg, oh, ol);
                }
            }
        }
        __syncthreads();
    }
    if (wid == 0) tc_dealloc(tmem, (NT > 128) ? 256 : 128);

#else  // ------------------- mma.sync fallback path -------------------------
    const int NTW = NT / 4;
    const int NNT = NT / 32;
    const int wm0 = (wid >> 2) * 64;
    const int wn0 = (wid & 3) * NTW;
    const int g = lid >> 2, tg = lid & 3;

    float acc[4][NT / 32][4];
    #pragma unroll
    for (int x = 0; x < 4; ++x)
        #pragma unroll
        for (int y = 0; y < NNT; ++y)
            #pragma unroll
            for (int c = 0; c < 4; ++c) acc[x][y][c] = 0.0f;

    load_chunk_cp<NT>(tile0, Ah, Al, Bh, Bl, bm, bn, N, K, 0, tid);

    for (int k = 0; k < nk; ++k) {
        const uint32_t oS = off0 + (uint32_t)(k & 1) * STG;
        if (k + 1 < nk) {
            load_chunk_cp<NT>(tile0 + ((k + 1) & 1) * STG,
                              Ah, Al, Bh, Bl, bm, bn, N, K, (k + 1) * 64, tid);
            asm volatile("cp.async.wait_group 1;" ::: "memory");
        } else {
            asm volatile("cp.async.wait_group 0;" ::: "memory");
        }
        __syncthreads();

        const uint32_t oA_h = oS, oA_l = oS + 16384;
        const uint32_t oB_h = oS + 32768, oB_l = oS + 32768 + NT * 128;

        #pragma unroll
        for (int ks = 0; ks < 4; ++ks) {
            const uint32_t kb = (uint32_t)(ks * 32 + tg * 4);
            uint32_t bh0[NT / 32], bh1[NT / 32], bl0[NT / 32], bl1[NT / 32];
            #pragma unroll
            for (int nt = 0; nt < NNT; ++nt) {
                uint32_t row = (uint32_t)(wn0 + nt * 8 + g);
                uint32_t o1 = row * 128 + kb;
                uint32_t o2 = o1 + 16;
                uint32_t s1 = o1 ^ ((o1 >> 3) & 0x70);
                uint32_t s2 = o2 ^ ((o2 >> 3) & 0x70);
                bh0[nt] = *(const uint32_t*)(smc + oB_h + s1);
                bh1[nt] = *(const uint32_t*)(smc + oB_h + s2);
                bl0[nt] = *(const uint32_t*)(smc + oB_l + s1);
                bl1[nt] = *(const uint32_t*)(smc + oB_l + s2);
            }
            #pragma unroll
            for (int mt = 0; mt < 4; ++mt) {
                uint32_t r0 = (uint32_t)(wm0 + mt * 16 + g);
                uint32_t o_r0c0 = r0 * 128 + kb;
                uint32_t o_r8c0 = o_r0c0 + 8 * 128;
                uint32_t o_r0c8 = o_r0c0 + 16;
                uint32_t o_r8c8 = o_r8c0 + 16;
                uint32_t s00 = o_r0c0 ^ ((o_r0c0 >> 3) & 0x70);
                uint32_t s80 = o_r8c0 ^ ((o_r8c0 >> 3) & 0x70);
                uint32_t s08 = o_r0c8 ^ ((o_r0c8 >> 3) & 0x70);
                uint32_t s88 = o_r8c8 ^ ((o_r8c8 >> 3) & 0x70);
                uint32_t ah0 = *(const uint32_t*)(smc + oA_h + s00);
                uint32_t ah1 = *(const uint32_t*)(smc + oA_h + s80);
                uint32_t ah2 = *(const uint32_t*)(smc + oA_h + s08);
                uint32_t ah3 = *(const uint32_t*)(smc + oA_h + s88);
                uint32_t al0 = *(const uint32_t*)(smc + oA_l + s00);
                uint32_t al1 = *(const uint32_t*)(smc + oA_l + s80);
                uint32_t al2 = *(const uint32_t*)(smc + oA_l + s08);
                uint32_t al3 = *(const uint32_t*)(smc + oA_l + s88);
                #pragma unroll
                for (int nt = 0; nt < NNT; ++nt) {
                    mma16816(acc[mt][nt], ah0, ah1, ah2, ah3, bh0[nt], bh1[nt]);
                    mma16816(acc[mt][nt], ah0, ah1, ah2, ah3, bl0[nt], bl1[nt]);
                    mma16816(acc[mt][nt], al0, al1, al2, al3, bh0[nt], bh1[nt]);
                }
            }
        }
        __syncthreads();
    }

    #pragma unroll
    for (int mt = 0; mt < 4; ++mt) {
        #pragma unroll
        for (int nt = 0; nt < NNT; ++nt) {
            int r0 = bm + wm0 + mt * 16 + g;
            int c0 = bn + wn0 + nt * 8 + tg * 2;
            #pragma unroll
            for (int half = 0; half < 2; ++half) {
                int row = r0 + half * 8;
                #pragma unroll
                for (int cc = 0; cc < 2; ++cc) {
                    int col = c0 + cc;
                    if (col < N)
                        epi_one<ACT, OUTMODE, NT>(row, col, acc[mt][nt][half*2+cc],
                                                  N, bias, Cf, Ch, Cl,
                                                  Yg, zg, xg, outg, oh, ol);
                }
            }
        }
    }
#endif
}

// ---------------------------------------------------------------------------
// Mega weight split
// ---------------------------------------------------------------------------
struct SArgs {
    const float4* s[8];
    uint2* h[8];
    uint2* l[8];
    int off[9];
};

__global__ __launch_bounds__(256)
void wsplit_all(SArgs a)
{
    int i = blockIdx.x * 256 + threadIdx.x;
    #pragma unroll
    for (int k = 0; k < 8; ++k) {
        if (i >= a.off[k] && i < a.off[k + 1]) {
            int j = i - a.off[k];
            pack4(a.s[k][j], a.h[k] + j, a.l[k] + j);
        }
    }
}

// ---------------------------------------------------------------------------
// LayerNorm (+ optional raw-input hi/lo split)
// ---------------------------------------------------------------------------
__global__ __launch_bounds__(256)
void ln_kernel(const float* __restrict__ x, const float* __restrict__ g,
               const float* __restrict__ b, bf16* __restrict__ yh,
               bf16* __restrict__ yl, bf16* __restrict__ rh,
               bf16* __restrict__ rl)
{
    __shared__ float rbuf[8];
    __shared__ float smean, srstd;
    const int row = blockIdx.x;
    const int tid = threadIdx.x;
    const int lane = tid & 31, warp = tid >> 5;
    const float* xr = x + (size_t)row * D_MODEL;

    float v0 = xr[tid], v1 = xr[tid + 256];
    size_t base = (size_t)row * D_MODEL;
    if (rh) {
        split1(v0, rh + base + tid,       rl + base + tid);
        split1(v1, rh + base + tid + 256, rl + base + tid + 256);
    }

    float s = warp_sum(v0 + v1);
    if (!lane) rbuf[warp] = s;
    __syncthreads();
    if (warp == 0) {
        float t = (lane < 8) ? rbuf[lane] : 0.0f;
        #pragma unroll
        for (int o = 4; o; o >>= 1) t += __shfl_down_sync(0xffffffffu, t, o);
        if (!lane) smean = t * (1.0f / D_MODEL);
    }
    __syncthreads();
    float m = smean;

    float d0 = v0 - m, d1 = v1 - m;
    float sv = warp_sum(d0 * d0 + d1 * d1);
    if (!lane) rbuf[warp] = sv;
    __syncthreads();
    if (warp == 0) {
        float t = (lane < 8) ? rbuf[lane] : 0.0f;
        #pragma unroll
        for (int o = 4; o; o >>= 1) t += __shfl_down_sync(0xffffffffu, t, o);
        if (!lane) srstd = rsqrtf(t * (1.0f / D_MODEL) + 1e-5f);
    }
    __syncthreads();
    float r = srstd;

    float o0 = d0 * r * g[tid]       + b[tid];
    float o1 = d1 * r * g[tid + 256] + b[tid + 256];
    split1(o0, yh + base + tid,       yl + base + tid);
    split1(o1, yh + base + tid + 256, yl + base + tid + 256);
}

// ---------------------------------------------------------------------------
// Fast scan: cp.async prefetch, socc table, 2 barriers/step, fast math
// ---------------------------------------------------------------------------
__global__ __launch_bounds__(256)
void scan_kernel(const float* __restrict__ allproj, const int* __restrict__ terms,
                 const float* __restrict__ tick, const float* __restrict__ tk,
                 const float* __restrict__ tv, const float* __restrict__ s_prev,
                 bf16* __restrict__ core_h, bf16* __restrict__ core_l)
{
    const int bh = blockIdx.x;
    const int b = bh >> 3, h = bh & 7;
    const int tid = threadIdx.x;
    const int lane = tid & 31, warp = tid >> 5;

    __shared__ float socc[T_][8];               // 4 KB
    __shared__ __align__(16) float buf[2][336];
    __shared__ float red[9 * 8];

    const float tickb = tick[b];
    for (int i = tid; i < T_ * 8; i += 256) {
        int t = i >> 3, u = i & 7;
        float om = -3.14159265358979323846f
                 + (float)u * (6.28318530717958647692f / 7.0f);
        socc[t][u] = cosf((tickb + (float)(t + 1)) * om);
    }

    float Kst[8], S;
    #pragma unroll
    for (int r = 0; r < 8; ++r)
        Kst[r] = tk[(((size_t)b * R_ + r) * H_ + h) * 256 + tid];
    S = s_prev[((size_t)b * H_ + h) * 256 + tid];
    float Vst[8];
    if (tid < 64) {
        #pragma unroll
        for (int r = 0; r < 8; ++r)
            Vst[r] = tv[(((size_t)b * R_ + r) * H_ + h) * 64 + tid];
    }

    const uint32_t sb0 = smem_u32(&buf[0][0]);
    const int d = tid >> 2, j = tid & 3;

    #define SCAN_PREFETCH(tt, sbuf) do {                                        \
        size_t rb_ = ((size_t)(tt) * B_ + b) * TOTAL_PROJ;                      \
        if (tid < 80)      cp16((sbuf) + tid * 16, allproj + rb_ + h * 320 + tid * 4); \
        else if (tid < 83) cp16((sbuf) + 1280 + (tid - 80) * 16,                \
                                allproj + rb_ + KQV_DIM + h * 12 + (tid - 80) * 4); \
        else if (tid == 83) cp4((sbuf) + 1328, terms + (tt) * B_ + b);          \
        cp_commit();                                                            \
    } while (0)

    SCAN_PREFETCH(0, sb0);
    __syncthreads();

    for (int t = 0; t < T_; ++t) {
        const float* cbuf = &buf[t & 1][0];
        if (t + 1 < T_) {
            SCAN_PREFETCH(t + 1, sb0 + ((t + 1) & 1) * 1344u);
            asm volatile("cp.async.wait_group 1;" ::: "memory");
        } else {
            asm volatile("cp.async.wait_group 0;" ::: "memory");
        }
        __syncthreads();

        const float term = 1.0f - (float)(*(const int*)&cbuf[332]);
        const float* oc = socc[t];

        float ke = fmaxf(cbuf[d], 0.0f)       * fmaxf(cbuf[320 + j], 0.0f);
        float qe = fmaxf(cbuf[64 + d], 0.0f)  * fmaxf(cbuf[324 + j], 0.0f);
        float ge = sigf(cbuf[256 + d])        * sigf(cbuf[328 + j]);
        float kg = ke * ge;
        float dg = (1.0f - ge) * term;
        S = fmaf(dg, S, kg);
        float loc[9];
        #pragma unroll
        for (int r = 0; r < 8; ++r) {
            Kst[r] = fmaf(dg, Kst[r], kg * oc[r]);
            loc[r] = Kst[r] * qe;
        }
        loc[8] = S * qe;

        if (tid < 64) {
            float bs = sigf(cbuf[192 + tid]);
            float vg = cbuf[128 + tid] * bs;
            float db = (1.0f - bs) * term;
            #pragma unroll
            for (int r = 0; r < 8; ++r)
                Vst[r] = fmaf(db, Vst[r], vg * oc[r]);
        }

        #pragma unroll
        for (int v = 0; v < 9; ++v) {
            float x = warp_sum(loc[v]);
            if (lane == 0) red[v * 8 + warp] = x;
        }
        __syncthreads();

        if (tid < 64) {
            float kdq[9];
            #pragma unroll
            for (int v = 0; v < 9; ++v) {
                kdq[v] = red[v * 8 + 0] + red[v * 8 + 1] + red[v * 8 + 2]
                       + red[v * 8 + 3] + red[v * 8 + 4] + red[v * 8 + 5]
                       + red[v * 8 + 6] + red[v * 8 + 7];
            }
            float kv = 0.0f;
            #pragma unroll
            for (int r = 0; r < 8; ++r) kv = fmaf(Vst[r], kdq[r], kv);
            float val = kv * 0.0625f * frcp_fast(kdq[8] + 1e-6f);
            size_t idx = ((size_t)t * B_ + b) * D_MODEL + h * 64 + tid;
            split1(val, core_h + idx, core_l + idx);
        }
    }
    #undef SCAN_PREFETCH
}

// ---------------------------------------------------------------------------
// GRU stage 1 (vectorized, fast sigmoid)
// ---------------------------------------------------------------------------
__global__ __launch_bounds__(256)
void gru_pre(const float4* __restrict__ x, const float* __restrict__ Y3,
             const float* __restrict__ X2, uint2* __restrict__ rxh,
             uint2* __restrict__ rxl, float4* __restrict__ z, int n4)
{
    int i = blockIdx.x * 256 + threadIdx.x;
    if (i >= n4) return;
    int row = i >> 7, c = (i & 127) * 4;
    const float4 y0 = *(const float4*)&Y3[(size_t)row * 1536 + c];
    const float4 y1 = *(const float4*)&Y3[(size_t)row * 1536 + 512 + c];
    const float4 x0 = *(const float4*)&X2[(size_t)row * 1024 + c];
    const float4 x1 = *(const float4*)&X2[(size_t)row * 1024 + 512 + c];
    float4 xv = x[i];
    float4 zz;
    zz.x = sigf(y1.x + x1.x - 2.0f);
    zz.y = sigf(y1.y + x1.y - 2.0f);
    zz.z = sigf(y1.z + x1.z - 2.0f);
    zz.w = sigf(y1.w + x1.w - 2.0f);
    float4 rx;
    rx.x = sigf(y0.x + x0.x) * xv.x;
    rx.y = sigf(y0.y + x0.y) * xv.y;
    rx.z = sigf(y0.z + x0.z) * xv.z;
    rx.w = sigf(y0.w + x0.w) * xv.w;
    z[i] = zz;
    pack4(rx, rxh + i, rxl + i);
}

// ---------------------------------------------------------------------------
// Launch
// ---------------------------------------------------------------------------
template<typename Tp>
static Tp* symptr(const void* sym) {
    void* p = nullptr;
    cudaGetSymbolAddress(&p, sym);
    return (Tp*)p;
}

extern "C" void kernel_launch(void* const* d_in, const int* in_sizes, int n_in,
                              void* d_out, int out_size)
{
    const float* inputs   = (const float*)d_in[0];
    const int*   terms    = (const int*)  d_in[1];
    const float* tilde_k  = (const float*)d_in[2];
    const float* tilde_v  = (const float*)d_in[3];
    const float* s_prev   = (const float*)d_in[4];
    const float* tick     = (const float*)d_in[5];
    const float* w_proj   = (const float*)d_in[6];
    const float* b_proj   = (const float*)d_in[7];
    const float* w_attn   = (const float*)d_in[8];
    const float* b_attn   = (const float*)d_in[9];
    const float* ln1_g    = (const float*)d_in[10];
    const float* ln1_b    = (const float*)d_in[11];
    const float* ln2_g    = (const float*)d_in[12];
    const float* ln2_b    = (const float*)d_in[13];
    const float* gru1_w   = (const float*)d_in[14];
    const float* gru1_u   = (const float*)d_in[15];
    const float* gru2_w   = (const float*)d_in[16];
    const float* gru2_u   = (const float*)d_in[17];
    const float* ffc_w1   = (const float*)d_in[18];
    const float* ffc_b1   = (const float*)d_in[19];
    const float* ffc_w2   = (const float*)d_in[20];
    const float* ffc_b2   = (const float*)d_in[21];
    float* out = (float*)d_out;

    float* allproj = symptr<float>(g_allproj);
    float* Y3   = symptr<float>(g_Y3);
    float* X2   = symptr<float>(g_X2);
    float* zb   = symptr<float>(g_zb);
    float* gate1= symptr<float>(g_gate1);

    bf16 *in_h = symptr<bf16>(g_in_h),  *in_l = symptr<bf16>(g_in_l);
    bf16 *xn_h = symptr<bf16>(g_xn_h),  *xn_l = symptr<bf16>(g_xn_l);
    bf16 *co_h = symptr<bf16>(g_core_h),*co_l = symptr<bf16>(g_core_l);
    bf16 *ar_h = symptr<bf16>(g_arelu_h),*ar_l= symptr<bf16>(g_arelu_l);
    bf16 *rx_h = symptr<bf16>(g_rx_h),  *rx_l = symptr<bf16>(g_rx_l);
    bf16 *g1_h = symptr<bf16>(g_g1_h),  *g1_l = symptr<bf16>(g_g1_l);
    bf16 *ff_h = symptr<bf16>(g_ff_h),  *ff_l = symptr<bf16>(g_ff_l);
    bf16 *hd_h = symptr<bf16>(g_hid_h), *hd_l = symptr<bf16>(g_hid_l);

    bf16 *wp_h = symptr<bf16>(g_wproj_h), *wp_l = symptr<bf16>(g_wproj_l);
    bf16 *wa_h = symptr<bf16>(g_wattn_h), *wa_l = symptr<bf16>(g_wattn_l);
    bf16 *w1w_h= symptr<bf16>(g_g1w_h),   *w1w_l= symptr<bf16>(g_g1w_l);
    bf16 *w1u_h= symptr<bf16>(g_g1u_h),   *w1u_l= symptr<bf16>(g_g1u_l);
    bf16 *w2w_h= symptr<bf16>(g_g2w_h),   *w2w_l= symptr<bf16>(g_g2w_l);
    bf16 *w2u_h= symptr<bf16>(g_g2u_h),   *w2u_l= symptr<bf16>(g_g2u_l);
    bf16 *f1_h = symptr<bf16>(g_fw1_h),   *f1_l = symptr<bf16>(g_fw1_l);
    bf16 *f2_h = symptr<bf16>(g_fw2_h),   *f2_l = symptr<bf16>(g_fw2_l);

    cudaFuncSetAttribute(gemm_tc<0,0,128>, cudaFuncAttributeMaxDynamicSharedMemorySize, SMEM_G(128));
    cudaFuncSetAttribute(gemm_tc<1,1,128>, cudaFuncAttributeMaxDynamicSharedMemorySize, SMEM_G(128));
    cudaFuncSetAttribute(gemm_tc<0,2,128>, cudaFuncAttributeMaxDynamicSharedMemorySize, SMEM_G(128));
    cudaFuncSetAttribute(gemm_tc<0,0,256>, cudaFuncAttributeMaxDynamicSharedMemorySize, SMEM_G(256));
    cudaFuncSetAttribute(gemm_tc<1,1,256>, cudaFuncAttributeMaxDynamicSharedMemorySize, SMEM_G(256));

    const int n = NTOK * D_MODEL;
    const int n4 = n / 4;
    dim3 thr(256);
    const int eg4 = (n4 + 255) / 256;
    const int OFF2 = 2 * D_MODEL * D_MODEL;

    // 1) ln1 + raw input split
    ln_kernel<<<NTOK, thr>>>(inputs, ln1_g, ln1_b, xn_h, xn_l, in_h, in_l);

    // 2) mega weight split
    {
        SArgs sa;
        const float* srcs[8] = {w_proj, w_attn, gru1_w, gru1_u,
                                gru2_w, gru2_u, ffc_w1, ffc_w2};
        bf16* hs[8] = {wp_h, wa_h, w1w_h, w1u_h, w2w_h, w2u_h, f1_h, f2_h};
        bf16* ls[8] = {wp_l, wa_l, w1w_l, w1u_l, w2w_l, w2u_l, f1_l, f2_l};
        int cnts[8] = {WPROJ_N, WATTN_N, WGRU_N, WGRU_N,
                       WGRU_N, WGRU_N, WFFC1_N, WFFC2_N};
        int acc = 0;
        for (int k = 0; k < 8; ++k) {
            sa.s[k] = (const float4*)srcs[k];
            sa.h[k] = (uint2*)hs[k];
            sa.l[k] = (uint2*)ls[k];
            sa.off[k] = acc;
            acc += cnts[k] / 4;
        }
        sa.off[8] = acc;
        wsplit_all<<<(acc + 255) / 256, thr>>>(sa);
    }

    // 3) proj GEMM (NT=256)
    gemm_tc<0,0,256><<<dim3((TOTAL_PROJ + 255) / 256, 32), thr, SMEM_G(256)>>>(
        xn_h, xn_l, wp_h, wp_l, b_proj, allproj, nullptr, nullptr,
        nullptr, nullptr, nullptr, nullptr, nullptr, nullptr,
        NTOK, TOTAL_PROJ, D_MODEL);

    // 4) scan
    scan_kernel<<<B_ * H_, thr>>>(allproj, terms, tick, tilde_k, tilde_v,
                                  s_prev, co_h, co_l);

    // 5) attn (relu, hi/lo)
    gemm_tc<1,1,128><<<dim3(4, 32), thr, SMEM_G(128)>>>(
        co_h, co_l, wa_h, wa_l, b_attn, nullptr, ar_h, ar_l,
        nullptr, nullptr, nullptr, nullptr, nullptr, nullptr,
        NTOK, D_MODEL, D_MODEL);

    // 6) GRU1 Y3
    gemm_tc<0,0,256><<<dim3(6, 32), thr, SMEM_G(256)>>>(
        ar_h, ar_l, w1w_h, w1w_l, nullptr, Y3, nullptr, nullptr,
        nullptr, nullptr, nullptr, nullptr, nullptr, nullptr,
        NTOK, 3 * D_MODEL, D_MODEL);

    // 7) GRU1 X2
    gemm_tc<0,0,256><<<dim3(4, 32), thr, SMEM_G(256)>>>(
        in_h, in_l, w1u_h, w1u_l, nullptr, X2, nullptr, nullptr,
        nullptr, nullptr, nullptr, nullptr, nullptr, nullptr,
        NTOK, 2 * D_MODEL, D_MODEL);

    // 8) gru_pre 1
    gru_pre<<<eg4, thr>>>((const float4*)inputs, Y3, X2,
                          (uint2*)rx_h, (uint2*)rx_l, (float4*)zb, n4);

    // 9) RX GEMM + fused gru_post -> gate1 (+hi/lo)
    gemm_tc<0,2,128><<<dim3(4, 32), thr, SMEM_G(128)>>>(
        rx_h, rx_l, w1u_h + OFF2, w1u_l + OFF2, nullptr, nullptr, nullptr, nullptr,
        Y3, zb, inputs, gate1, g1_h, g1_l,
        NTOK, D_MODEL, D_MODEL);

    // 10) ln2
    ln_kernel<<<NTOK, thr>>>(gate1, ln2_g, ln2_b, xn_h, xn_l, nullptr, nullptr);

    // 11) FFC1 (relu, hi/lo)
    gemm_tc<1,1,256><<<dim3(8, 32), thr, SMEM_G(256)>>>(
        xn_h, xn_l, f1_h, f1_l, ffc_b1, nullptr, hd_h, hd_l,
        nullptr, nullptr, nullptr, nullptr, nullptr, nullptr,
        NTOK, D_FFC, D_MODEL);

    // 12) FFC2 (relu, hi/lo)
    gemm_tc<1,1,128><<<dim3(4, 32), thr, SMEM_G(128)>>>(
        hd_h, hd_l, f2_h, f2_l, ffc_b2, nullptr, ff_h, ff_l,
        nullptr, nullptr, nullptr, nullptr, nullptr, nullptr,
        NTOK, D_MODEL, D_FFC);

    // 13) GRU2 Y3
    gemm_tc<0,0,256><<<dim3(6, 32), thr, SMEM_G(256)>>>(
        ff_h, ff_l, w2w_h, w2w_l, nullptr, Y3, nullptr, nullptr,
        nullptr, nullptr, nullptr, nullptr, nullptr, nullptr,
        NTOK, 3 * D_MODEL, D_MODEL);

    // 14) GRU2 X2
    gemm_tc<0,0,256><<<dim3(4, 32), thr, SMEM_G(256)>>>(
        g1_h, g1_l, w2u_h, w2u_l, nullptr, X2, nullptr, nullptr,
        nullptr, nullptr, nullptr, nullptr, nullptr, nullptr,
        NTOK, 2 * D_MODEL, D_MODEL);

    // 15) gru_pre 2
    gru_pre<<<eg4, thr>>>((const float4*)gate1, Y3, X2,
                          (uint2*)rx_h, (uint2*)rx_l, (float4*)zb, n4);

    // 16) RX GEMM + fused gru_post -> out
    gemm_tc<0,2,128><<<dim3(4, 32), thr, SMEM_G(128)>>>(
        rx_h, rx_l, w2u_h + OFF2, w2u_l + OFF2, nullptr, nullptr, nullptr, nullptr,
        Y3, zb, gate1, out, nullptr, nullptr,
        NTOK, D_MODEL, D_MODEL);
}

// round 14
// speedup vs baseline: 1.9134x; 1.0139x over previous
#include <cuda_runtime.h>
#include <cuda_bf16.h>
#include <math.h>
#include <stdint.h>

// Problem constants
#define D_MODEL 512
#define H_ 8
#define HD_ 64
#define ETA_ 4
#define R_ 8
#define D_FFC 2048
#define T_ 128
#define B_ 32
#define NTOK (T_*B_)            // 4096
#define TOTAL_PROJ 2656
#define KQV_DIM 2560

typedef __nv_bfloat16 bf16;

#if defined(__CUDA_ARCH_FEAT_SM103_ALL) || defined(__CUDA_ARCH_FEAT_SM100_ALL)
#define HAS_TCGEN05 1
#else
#define HAS_TCGEN05 0
#endif

// ---------------------------------------------------------------------------
// Scratch
// ---------------------------------------------------------------------------
__device__ float g_allproj[NTOK * TOTAL_PROJ];
__device__ float g_Y3   [NTOK * 3 * D_MODEL];
__device__ float g_X2   [NTOK * 2 * D_MODEL];
__device__ float g_zb   [NTOK * D_MODEL];
__device__ float g_gate1[NTOK * D_MODEL];

__device__ __align__(256) bf16 g_in_h   [NTOK * D_MODEL], g_in_l   [NTOK * D_MODEL];
__device__ __align__(256) bf16 g_xn_h   [NTOK * D_MODEL], g_xn_l   [NTOK * D_MODEL];
__device__ __align__(256) bf16 g_core_h [NTOK * D_MODEL], g_core_l [NTOK * D_MODEL];
__device__ __align__(256) bf16 g_arelu_h[NTOK * D_MODEL], g_arelu_l[NTOK * D_MODEL];
__device__ __align__(256) bf16 g_rx_h   [NTOK * D_MODEL], g_rx_l   [NTOK * D_MODEL];
__device__ __align__(256) bf16 g_g1_h   [NTOK * D_MODEL], g_g1_l   [NTOK * D_MODEL];
__device__ __align__(256) bf16 g_ff_h   [NTOK * D_MODEL], g_ff_l   [NTOK * D_MODEL];
__device__ __align__(256) bf16 g_hid_h  [NTOK * D_FFC],   g_hid_l  [NTOK * D_FFC];

#define WPROJ_N (TOTAL_PROJ * D_MODEL)
#define WATTN_N (D_MODEL * D_MODEL)
#define WGRU_N  (3 * D_MODEL * D_MODEL)
#define WFFC1_N (D_FFC * D_MODEL)
#define WFFC2_N (D_MODEL * D_FFC)
__device__ __align__(256) bf16 g_wproj_h[WPROJ_N], g_wproj_l[WPROJ_N];
__device__ __align__(256) bf16 g_wattn_h[WATTN_N], g_wattn_l[WATTN_N];
__device__ __align__(256) bf16 g_g1w_h[WGRU_N], g_g1w_l[WGRU_N];
__device__ __align__(256) bf16 g_g1u_h[WGRU_N], g_g1u_l[WGRU_N];
__device__ __align__(256) bf16 g_g2w_h[WGRU_N], g_g2w_l[WGRU_N];
__device__ __align__(256) bf16 g_g2u_h[WGRU_N], g_g2u_l[WGRU_N];
__device__ __align__(256) bf16 g_fw1_h[WFFC1_N], g_fw1_l[WFFC1_N];
__device__ __align__(256) bf16 g_fw2_h[WFFC2_N], g_fw2_l[WFFC2_N];

// ---------------------------------------------------------------------------
// Fast math helpers (error ~1e-6 relative; rel_err budget is 1e-3)
// ---------------------------------------------------------------------------
__device__ __forceinline__ float frcp_fast(float x) {
    float r;
    asm("rcp.approx.f32 %0, %1;" : "=f"(r) : "f"(x));
    return r;
}
__device__ __forceinline__ float sigf(float x) {
    return frcp_fast(1.0f + __expf(-x));
}
__device__ __forceinline__ float tanh_fast(float x) {
    return 1.0f - 2.0f * frcp_fast(__expf(2.0f * x) + 1.0f);
}

__device__ __forceinline__ void split1(float v, bf16* h, bf16* l) {
    bf16 hv = __float2bfloat16(v);
    *h = hv;
    *l = __float2bfloat16(v - __bfloat162float(hv));
}

__device__ __forceinline__ void pack4(float4 v, uint2* hp, uint2* lp) {
    bf16 h0 = __float2bfloat16(v.x), h1 = __float2bfloat16(v.y);
    bf16 h2 = __float2bfloat16(v.z), h3 = __float2bfloat16(v.w);
    bf16 l0 = __float2bfloat16(v.x - __bfloat162float(h0));
    bf16 l1 = __float2bfloat16(v.y - __bfloat162float(h1));
    bf16 l2 = __float2bfloat16(v.z - __bfloat162float(h2));
    bf16 l3 = __float2bfloat16(v.w - __bfloat162float(h3));
    __nv_bfloat162 ha = __halves2bfloat162(h0, h1), hb = __halves2bfloat162(h2, h3);
    __nv_bfloat162 la = __halves2bfloat162(l0, l1), lb = __halves2bfloat162(l2, l3);
    uint2 hh, ll;
    hh.x = *reinterpret_cast<uint32_t*>(&ha);
    hh.y = *reinterpret_cast<uint32_t*>(&hb);
    ll.x = *reinterpret_cast<uint32_t*>(&la);
    ll.y = *reinterpret_cast<uint32_t*>(&lb);
    *hp = hh;
    *lp = ll;
}

__device__ __forceinline__ uint32_t smem_u32(const void* p) {
    uint32_t a;
    asm("{ .reg .u64 t; cvta.to.shared.u64 t, %1; cvt.u32.u64 %0, t; }"
        : "=r"(a) : "l"(p));
    return a;
}

__device__ __forceinline__ void cp16(uint32_t dst, const void* src) {
    asm volatile("cp.async.cg.shared.global [%0], [%1], 16;"
                 :: "r"(dst), "l"(src));
}
__device__ __forceinline__ void cp16z(uint32_t dst, const void* src, int sz) {
    asm volatile("cp.async.cg.shared.global [%0], [%1], 16, %2;"
                 :: "r"(dst), "l"(src), "r"(sz));
}
__device__ __forceinline__ void cp4(uint32_t dst, const void* src) {
    asm volatile("cp.async.ca.shared.global [%0], [%1], 4;"
                 :: "r"(dst), "l"(src));
}
__device__ __forceinline__ void cp_commit() {
    asm volatile("cp.async.commit_group;" ::: "memory");
}

// Warp sum (valid in lane 0)
__device__ __forceinline__ float warp_sum(float x) {
    x += __shfl_down_sync(0xffffffffu, x, 16);
    x += __shfl_down_sync(0xffffffffu, x, 8);
    x += __shfl_down_sync(0xffffffffu, x, 4);
    x += __shfl_down_sync(0xffffffffu, x, 2);
    x += __shfl_down_sync(0xffffffffu, x, 1);
    return x;
}

template<int NT>
__device__ __forceinline__ void load_chunk_cp(
    uint32_t sb, const bf16* Ah, const bf16* Al,
    const bf16* Bh, const bf16* Bl,
    int bm, int bn, int N, int K, int k0, int tid)
{
    #pragma unroll
    for (int p = 0; p < 4; ++p) {
        int id = tid + p * 256;
        int row = id >> 3, grp = id & 7;
        uint32_t boff = (uint32_t)(row * 128 + grp * 16);
        uint32_t sw = boff ^ ((boff >> 3) & 0x70);
        size_t ao = (size_t)(bm + row) * K + k0 + grp * 8;
        cp16(sb + sw,         Ah + ao);
        cp16(sb + 16384 + sw, Al + ao);
    }
    const uint32_t bBh = sb + 32768;
    const uint32_t bBl = sb + 32768 + NT * 128;
    #pragma unroll
    for (int p = 0; p < NT / 32; ++p) {
        int id = tid + p * 256;
        int row = id >> 3, grp = id & 7;
        uint32_t boff = (uint32_t)(row * 128 + grp * 16);
        uint32_t sw = boff ^ ((boff >> 3) & 0x70);
        int brow = bn + row;
        int ok = (brow < N) ? 16 : 0;
        size_t bo = (size_t)(brow < N ? brow : 0) * K + k0 + grp * 8;
        cp16z(bBh + sw, Bh + bo, ok);
        cp16z(bBl + sw, Bl + bo, ok);
    }
    cp_commit();
}

#if HAS_TCGEN05
__device__ __forceinline__ uint32_t elect1() {
    uint32_t r;
    asm volatile("{\n\t.reg .pred p;\n\telect.sync _|p, 0xFFFFFFFF;\n\t"
                 "selp.b32 %0,1,0,p;\n\t}" : "=r"(r));
    return r;
}
__device__ __forceinline__ void tc_alloc(uint32_t saddr, uint32_t ncols) {
    asm volatile("tcgen05.alloc.cta_group::1.sync.aligned.shared::cta.b32 [%0], %1;"
                 :: "r"(saddr), "r"(ncols) : "memory");
}
__device__ __forceinline__ void tc_relinq() {
    asm volatile("tcgen05.relinquish_alloc_permit.cta_group::1.sync.aligned;");
}
__device__ __forceinline__ void tc_dealloc(uint32_t tmem, uint32_t ncols) {
    asm volatile("tcgen05.dealloc.cta_group::1.sync.aligned.b32 %0, %1;"
                 :: "r"(tmem), "r"(ncols));
}
__device__ __forceinline__ void mbar_init(uint32_t mb, uint32_t cnt) {
    asm volatile("mbarrier.init.shared.b64 [%0], %1;" :: "r"(mb), "r"(cnt) : "memory");
}
__device__ __forceinline__ void mbar_wait(uint32_t mb, uint32_t parity) {
    asm volatile("{\n\t.reg .pred P;\n\t"
                 "WL_%=:\n\t"
                 "mbarrier.try_wait.parity.acquire.cta.shared::cta.b64 P, [%0], %1, 0x989680;\n\t"
                 "@!P bra WL_%=;\n\t}"
                 :: "r"(mb), "r"(parity) : "memory");
}
__device__ __forceinline__ void tc_commit(uint32_t mb) {
    asm volatile("tcgen05.commit.cta_group::1.mbarrier::arrive::one.shared::cluster.b64 [%0];"
                 :: "r"(mb) : "memory");
}
__device__ __forceinline__ void fence_async_smem() {
    asm volatile("fence.proxy.async.shared::cta;" ::: "memory");
}
__device__ __forceinline__ void tc_fence_after() {
    asm volatile("tcgen05.fence::after_thread_sync;" ::: "memory");
}
__device__ __forceinline__ void tc_wait_ld() {
    asm volatile("tcgen05.wait::ld.sync.aligned;" ::: "memory");
}
__device__ __forceinline__ void mma_ss(uint32_t d, uint64_t a, uint64_t b,
                                       uint32_t idesc, bool en) {
    uint32_t e = en ? 1u : 0u;
    asm volatile("{\n\t.reg .pred p;\n\tsetp.ne.u32 p, %4, 0;\n\t"
                 "tcgen05.mma.cta_group::1.kind::f16 [%0], %1, %2, %3, "
                 "{%5, %5, %5, %5}, p;\n\t}"
                 :: "r"(d), "l"(a), "l"(b), "r"(idesc), "r"(e), "r"(0u)
                 : "memory");
}
__device__ __forceinline__ void ldtm32(uint32_t* r, uint32_t tmem) {
    asm volatile(
        "tcgen05.ld.sync.aligned.32x32b.x32.b32 "
        "{%0, %1, %2, %3, %4, %5, %6, %7, %8, %9, %10, %11, %12, %13, %14, %15, "
        "%16, %17, %18, %19, %20, %21, %22, %23, %24, %25, %26, %27, %28, %29, %30, %31}, [%32];"
        : "=r"(r[0]), "=r"(r[1]), "=r"(r[2]), "=r"(r[3]),
          "=r"(r[4]), "=r"(r[5]), "=r"(r[6]), "=r"(r[7]),
          "=r"(r[8]), "=r"(r[9]), "=r"(r[10]), "=r"(r[11]),
          "=r"(r[12]), "=r"(r[13]), "=r"(r[14]), "=r"(r[15]),
          "=r"(r[16]), "=r"(r[17]), "=r"(r[18]), "=r"(r[19]),
          "=r"(r[20]), "=r"(r[21]), "=r"(r[22]), "=r"(r[23]),
          "=r"(r[24]), "=r"(r[25]), "=r"(r[26]), "=r"(r[27]),
          "=r"(r[28]), "=r"(r[29]), "=r"(r[30]), "=r"(r[31])
        : "r"(tmem));
}
__device__ __forceinline__ uint64_t mk_desc(uint32_t saddr) {
    const uint64_t base = (uint64_t(2) << 61) | (uint64_t(1) << 46)
                        | (uint64_t(64) << 32) | (uint64_t(1) << 16);
    return base | ((uint64_t)(saddr >> 4) & 0x3FFF);
}
#define IDESC_128 ((1u << 4) | (1u << 7) | (1u << 10) | (16u << 17) | (8u << 24))
#endif // HAS_TCGEN05

__device__ __forceinline__ void mma16816(float* d, uint32_t a0, uint32_t a1,
                                         uint32_t a2, uint32_t a3,
                                         uint32_t b0, uint32_t b1) {
    asm volatile(
        "mma.sync.aligned.m16n8k16.row.col.f32.bf16.bf16.f32 "
        "{%0,%1,%2,%3}, {%4,%5,%6,%7}, {%8,%9}, {%0,%1,%2,%3};"
        : "+f"(d[0]), "+f"(d[1]), "+f"(d[2]), "+f"(d[3])
        : "r"(a0), "r"(a1), "r"(a2), "r"(a3), "r"(b0), "r"(b1));
}

// ---------------------------------------------------------------------------
// bf16-split GEMM: compile-time template.
// OUTMODE: 0 = fp32, 1 = (relu?)+bf16 hi/lo, 2 = fused GRU-post (N=512)
// ---------------------------------------------------------------------------
#define STAGE_B(NT) (32768 + 2 * (NT) * 128)
#define SMEM_G(NT)  (1024 + 2 * STAGE_B(NT) + 1024)

template<int ACT, int OUTMODE, int NT>
__device__ __forceinline__ void epi_one(
    int row, int col, float v, int N,
    const float* __restrict__ bias,
    float* __restrict__ Cf, bf16* __restrict__ Ch, bf16* __restrict__ Cl,
    const float* __restrict__ Yg, const float* __restrict__ zg,
    const float* __restrict__ xg, float* __restrict__ outg,
    bf16* __restrict__ oh, bf16* __restrict__ ol)
{
    if (OUTMODE == 2) {
        float yv = Yg[(size_t)row * 1536 + 1024 + col];
        float hh = tanh_fast(yv + v);
        size_t e = (size_t)row * 512 + col;
        float zz = zg[e];
        float o = (1.0f - zz) * xg[e] + zz * hh;
        outg[e] = o;
        if (oh) split1(o, oh + e, ol + e);
    } else {
        if (bias) v += bias[col];
        if (ACT) v = fmaxf(v, 0.0f);
        size_t idx = (size_t)row * N + col;
        if (OUTMODE == 0) {
            Cf[idx] = v;
        } else {
            bf16 h = __float2bfloat16(v);
            Ch[idx] = h;
            Cl[idx] = __float2bfloat16(v - __bfloat162float(h));
        }
    }
}

template<int ACT, int OUTMODE, int NT>
__global__ __launch_bounds__(256)
void gemm_tc(const bf16* __restrict__ Ah, const bf16* __restrict__ Al,
             const bf16* __restrict__ Bh, const bf16* __restrict__ Bl,
             const float* __restrict__ bias,
             float* __restrict__ Cf, bf16* __restrict__ Ch, bf16* __restrict__ Cl,
             const float* __restrict__ Yg, const float* __restrict__ zg,
             const float* __restrict__ xg, float* __restrict__ outg,
             bf16* __restrict__ oh, bf16* __restrict__ ol,
             int M, int N, int K)
{
    extern __shared__ char dsm[];
    const uint32_t sraw = smem_u32(dsm);
    const uint32_t tile0 = (sraw + 1024u) & ~1023u;
    const uint32_t off0 = tile0 - sraw;
    const uint32_t STG = STAGE_B(NT);

    const int tid = threadIdx.x;
    const int wid = tid >> 5, lid = tid & 31;
    const int bm = blockIdx.y * 128;
    const int bn = blockIdx.x * NT;
    char* smc = dsm;
    const int nk = K >> 6;

#if HAS_TCGEN05
    const uint32_t mb0 = sraw + 8, mb1 = sraw + 16;

    if (wid == 0) { tc_alloc(sraw, (NT > 128) ? 256 : 128); tc_relinq(); }
    if (tid == 0) { mbar_init(mb0, 1); mbar_init(mb1, 1); }
    __syncthreads();
    uint32_t tmem;
    asm volatile("ld.shared.b32 %0, [%1];" : "=r"(tmem) : "r"(sraw));

    load_chunk_cp<NT>(tile0, Ah, Al, Bh, Bl, bm, bn, N, K, 0, tid);

    int ph0 = 0, ph1 = 0;
    for (int k = 0; k < nk; ++k) {
        const int s = k & 1;
        if (k + 1 < nk) {
            if (k >= 1) {
                if (((k + 1) & 1) == 0) { mbar_wait(mb0, ph0); ph0 ^= 1; }
                else                    { mbar_wait(mb1, ph1); ph1 ^= 1; }
            }
            load_chunk_cp<NT>(tile0 + ((k + 1) & 1) * STG,
                              Ah, Al, Bh, Bl, bm, bn, N, K, (k + 1) * 64, tid);
            asm volatile("cp.async.wait_group 1;" ::: "memory");
        } else {
            asm volatile("cp.async.wait_group 0;" ::: "memory");
        }
        fence_async_smem();
        __syncthreads();

        if (wid == 0) {
            if (elect1()) {
                uint32_t base = tile0 + s * STG;
                uint64_t dah = mk_desc(base);
                uint64_t dal = mk_desc(base + 16384);
                uint64_t dbh = mk_desc(base + 32768);
                uint64_t dbl = mk_desc(base + 32768 + NT * 128);
                #pragma unroll
                for (int ks = 0; ks < 4; ++ks) {
                    uint64_t o = (uint64_t)(ks * 2);
                    bool en0 = (k > 0) || (ks > 0);
                    mma_ss(tmem, dah + o, dbh + o, IDESC_128, en0);
                    mma_ss(tmem, dah + o, dbl + o, IDESC_128, true);
                    mma_ss(tmem, dal + o, dbh + o, IDESC_128, true);
                    if (NT > 128) {
                        mma_ss(tmem + 128, dah + o, dbh + 1024 + o, IDESC_128, en0);
                        mma_ss(tmem + 128, dah + o, dbl + 1024 + o, IDESC_128, true);
                        mma_ss(tmem + 128, dal + o, dbh + 1024 + o, IDESC_128, true);
                    }
                }
                tc_commit(s == 0 ? mb0 : mb1);
            }
        }
    }
    if (((nk - 1) & 1) == 0) mbar_wait(mb0, ph0);
    else                     mbar_wait(mb1, ph1);
    tc_fence_after();
    __syncthreads();

    float* sf = (float*)(smc + off0);
    #pragma unroll
    for (int nb = 0; nb < NT / 32; ++nb) {
        if (wid < 4) {
            uint32_t dr[32];
            ldtm32(dr, tmem + nb * 32);
            tc_wait_ld();
            int mrow = wid * 32 + lid;
            #pragma unroll
            for (int c = 0; c < 32; ++c) sf[mrow * 33 + c] = __uint_as_float(dr[c]);
        }
        __syncthreads();
        int cb = bn + nb * 32;
        if (cb < N) {
            int col = cb + lid;
            if (col < N) {
                int rbase = (tid >> 5) * 16;
                #pragma unroll
                for (int rr = 0; rr < 16; ++rr) {
                    int row = rbase + rr;
                    epi_one<ACT, OUTMODE, NT>(bm + row, col, sf[row * 33 + lid],
                                              N, bias, Cf, Ch, Cl,
                                              Yg, zg, xg, outg, oh, ol);
                }
            }
        }
        __syncthreads();
    }
    if (wid == 0) tc_dealloc(tmem, (NT > 128) ? 256 : 128);

#else  // ------------------- mma.sync fallback path -------------------------
    const int NTW = NT / 4;
    const int NNT = NT / 32;
    const int wm0 = (wid >> 2) * 64;
    const int wn0 = (wid & 3) * NTW;
    const int g = lid >> 2, tg = lid & 3;

    float acc[4][NT / 32][4];
    #pragma unroll
    for (int x = 0; x < 4; ++x)
        #pragma unroll
        for (int y = 0; y < NNT; ++y)
            #pragma unroll
            for (int c = 0; c < 4; ++c) acc[x][y][c] = 0.0f;

    load_chunk_cp<NT>(tile0, Ah, Al, Bh, Bl, bm, bn, N, K, 0, tid);

    for (int k = 0; k < nk; ++k) {
        const uint32_t oS = off0 + (uint32_t)(k & 1) * STG;
        if (k + 1 < nk) {
            load_chunk_cp<NT>(tile0 + ((k + 1) & 1) * STG,
                              Ah, Al, Bh, Bl, bm, bn, N, K, (k + 1) * 64, tid);
            asm volatile("cp.async.wait_group 1;" ::: "memory");
        } else {
            asm volatile("cp.async.wait_group 0;" ::: "memory");
        }
        __syncthreads();

        const uint32_t oA_h = oS, oA_l = oS + 16384;
        const uint32_t oB_h = oS + 32768, oB_l = oS + 32768 + NT * 128;

        #pragma unroll
        for (int ks = 0; ks < 4; ++ks) {
            const uint32_t kb = (uint32_t)(ks * 32 + tg * 4);
            uint32_t bh0[NT / 32], bh1[NT / 32], bl0[NT / 32], bl1[NT / 32];
            #pragma unroll
            for (int nt = 0; nt < NNT; ++nt) {
                uint32_t row = (uint32_t)(wn0 + nt * 8 + g);
                uint32_t o1 = row * 128 + kb;
                uint32_t o2 = o1 + 16;
                uint32_t s1 = o1 ^ ((o1 >> 3) & 0x70);
                uint32_t s2 = o2 ^ ((o2 >> 3) & 0x70);
                bh0[nt] = *(const uint32_t*)(smc + oB_h + s1);
                bh1[nt] = *(const uint32_t*)(smc + oB_h + s2);
                bl0[nt] = *(const uint32_t*)(smc + oB_l + s1);
                bl1[nt] = *(const uint32_t*)(smc + oB_l + s2);
            }
            #pragma unroll
            for (int mt = 0; mt < 4; ++mt) {
                uint32_t r0 = (uint32_t)(wm0 + mt * 16 + g);
                uint32_t o_r0c0 = r0 * 128 + kb;
                uint32_t o_r8c0 = o_r0c0 + 8 * 128;
                uint32_t o_r0c8 = o_r0c0 + 16;
                uint32_t o_r8c8 = o_r8c0 + 16;
                uint32_t s00 = o_r0c0 ^ ((o_r0c0 >> 3) & 0x70);
                uint32_t s80 = o_r8c0 ^ ((o_r8c0 >> 3) & 0x70);
                uint32_t s08 = o_r0c8 ^ ((o_r0c8 >> 3) & 0x70);
                uint32_t s88 = o_r8c8 ^ ((o_r8c8 >> 3) & 0x70);
                uint32_t ah0 = *(const uint32_t*)(smc + oA_h + s00);
                uint32_t ah1 = *(const uint32_t*)(smc + oA_h + s80);
                uint32_t ah2 = *(const uint32_t*)(smc + oA_h + s08);
                uint32_t ah3 = *(const uint32_t*)(smc + oA_h + s88);
                uint32_t al0 = *(const uint32_t*)(smc + oA_l + s00);
                uint32_t al1 = *(const uint32_t*)(smc + oA_l + s80);
                uint32_t al2 = *(const uint32_t*)(smc + oA_l + s08);
                uint32_t al3 = *(const uint32_t*)(smc + oA_l + s88);
                #pragma unroll
                for (int nt = 0; nt < NNT; ++nt) {
                    mma16816(acc[mt][nt], ah0, ah1, ah2, ah3, bh0[nt], bh1[nt]);
                    mma16816(acc[mt][nt], ah0, ah1, ah2, ah3, bl0[nt], bl1[nt]);
                    mma16816(acc[mt][nt], al0, al1, al2, al3, bh0[nt], bh1[nt]);
                }
            }
        }
        __syncthreads();
    }

    #pragma unroll
    for (int mt = 0; mt < 4; ++mt) {
        #pragma unroll
        for (int nt = 0; nt < NNT; ++nt) {
            int r0 = bm + wm0 + mt * 16 + g;
            int c0 = bn + wn0 + nt * 8 + tg * 2;
            #pragma unroll
            for (int half = 0; half < 2; ++half) {
                int row = r0 + half * 8;
                #pragma unroll
                for (int cc = 0; cc < 2; ++cc) {
                    int col = c0 + cc;
                    if (col < N)
                        epi_one<ACT, OUTMODE, NT>(row, col, acc[mt][nt][half*2+cc],
                                                  N, bias, Cf, Ch, Cl,
                                                  Yg, zg, xg, outg, oh, ol);
                }
            }
        }
    }
#endif
}

// ---------------------------------------------------------------------------
// Mega weight split
// ---------------------------------------------------------------------------
struct SArgs {
    const float4* s[8];
    uint2* h[8];
    uint2* l[8];
    int off[9];
};

__global__ __launch_bounds__(256)
void wsplit_all(SArgs a)
{
    int i = blockIdx.x * 256 + threadIdx.x;
    #pragma unroll
    for (int k = 0; k < 8; ++k) {
        if (i >= a.off[k] && i < a.off[k + 1]) {
            int j = i - a.off[k];
            pack4(a.s[k][j], a.h[k] + j, a.l[k] + j);
        }
    }
}

// ---------------------------------------------------------------------------
// LayerNorm (+ optional raw-input hi/lo split)
// ---------------------------------------------------------------------------
__global__ __launch_bounds__(256)
void ln_kernel(const float* __restrict__ x, const float* __restrict__ g,
               const float* __restrict__ b, bf16* __restrict__ yh,
               bf16* __restrict__ yl, bf16* __restrict__ rh,
               bf16* __restrict__ rl)
{
    __shared__ float rbuf[8];
    __shared__ float smean, srstd;
    const int row = blockIdx.x;
    const int tid = threadIdx.x;
    const int lane = tid & 31, warp = tid >> 5;
    const float* xr = x + (size_t)row * D_MODEL;

    float v0 = xr[tid], v1 = xr[tid + 256];
    size_t base = (size_t)row * D_MODEL;
    if (rh) {
        split1(v0, rh + base + tid,       rl + base + tid);
        split1(v1, rh + base + tid + 256, rl + base + tid + 256);
    }

    float s = warp_sum(v0 + v1);
    if (!lane) rbuf[warp] = s;
    __syncthreads();
    if (warp == 0) {
        float t = (lane < 8) ? rbuf[lane] : 0.0f;
        #pragma unroll
        for (int o = 4; o; o >>= 1) t += __shfl_down_sync(0xffffffffu, t, o);
        if (!lane) smean = t * (1.0f / D_MODEL);
    }
    __syncthreads();
    float m = smean;

    float d0 = v0 - m, d1 = v1 - m;
    float sv = warp_sum(d0 * d0 + d1 * d1);
    if (!lane) rbuf[warp] = sv;
    __syncthreads();
    if (warp == 0) {
        float t = (lane < 8) ? rbuf[lane] : 0.0f;
        #pragma unroll
        for (int o = 4; o; o >>= 1) t += __shfl_down_sync(0xffffffffu, t, o);
        if (!lane) srstd = rsqrtf(t * (1.0f / D_MODEL) + 1e-5f);
    }
    __syncthreads();
    float r = srstd;

    float o0 = d0 * r * g[tid]       + b[tid];
    float o1 = d1 * r * g[tid + 256] + b[tid + 256];
    split1(o0, yh + base + tid,       yl + base + tid);
    split1(o1, yh + base + tid + 256, yl + base + tid + 256);
}

// ---------------------------------------------------------------------------
// Fast scan: cp.async prefetch, socc table, smem transpose-reduce
//   - thread e stores 9 partials to sloc[e*13 + v] (pad 13: conflict-free)
//   - warp w reduces value w over e (warp 7 also value 8)
//   - 64 finalize threads read 9 broadcast kdqs
// ---------------------------------------------------------------------------
__global__ __launch_bounds__(256)
void scan_kernel(const float* __restrict__ allproj, const int* __restrict__ terms,
                 const float* __restrict__ tick, const float* __restrict__ tk,
                 const float* __restrict__ tv, const float* __restrict__ s_prev,
                 bf16* __restrict__ core_h, bf16* __restrict__ core_l)
{
    const int bh = blockIdx.x;
    const int b = bh >> 3, h = bh & 7;
    const int tid = threadIdx.x;
    const int lane = tid & 31, warp = tid >> 5;

    __shared__ float socc[T_][8];               // 4 KB
    __shared__ __align__(16) float buf[2][336];
    __shared__ float sloc[256 * 13];            // 13 KB, pad-13
    __shared__ float kdqs[16];

    const float tickb = tick[b];
    for (int i = tid; i < T_ * 8; i += 256) {
        int t = i >> 3, u = i & 7;
        float om = -3.14159265358979323846f
                 + (float)u * (6.28318530717958647692f / 7.0f);
        socc[t][u] = cosf((tickb + (float)(t + 1)) * om);
    }

    float Kst[8], S;
    #pragma unroll
    for (int r = 0; r < 8; ++r)
        Kst[r] = tk[(((size_t)b * R_ + r) * H_ + h) * 256 + tid];
    S = s_prev[((size_t)b * H_ + h) * 256 + tid];
    float Vst[8];
    if (tid < 64) {
        #pragma unroll
        for (int r = 0; r < 8; ++r)
            Vst[r] = tv[(((size_t)b * R_ + r) * H_ + h) * 64 + tid];
    }

    const uint32_t sb0 = smem_u32(&buf[0][0]);
    const int d = tid >> 2, j = tid & 3;

    #define SCAN_PREFETCH(tt, sbuf) do {                                        \
        size_t rb_ = ((size_t)(tt) * B_ + b) * TOTAL_PROJ;                      \
        if (tid < 80)      cp16((sbuf) + tid * 16, allproj + rb_ + h * 320 + tid * 4); \
        else if (tid < 83) cp16((sbuf) + 1280 + (tid - 80) * 16,                \
                                allproj + rb_ + KQV_DIM + h * 12 + (tid - 80) * 4); \
        else if (tid == 83) cp4((sbuf) + 1328, terms + (tt) * B_ + b);          \
        cp_commit();                                                            \
    } while (0)

    SCAN_PREFETCH(0, sb0);
    __syncthreads();

    for (int t = 0; t < T_; ++t) {
        const float* cbuf = &buf[t & 1][0];
        if (t + 1 < T_) {
            SCAN_PREFETCH(t + 1, sb0 + ((t + 1) & 1) * 1344u);
            asm volatile("cp.async.wait_group 1;" ::: "memory");
        } else {
            asm volatile("cp.async.wait_group 0;" ::: "memory");
        }
        __syncthreads();   // bar1: buf ready; prev finalize done

        const float term = 1.0f - (float)(*(const int*)&cbuf[332]);
        const float* oc = socc[t];

        // --- K / S side (thread = e) ---
        float ke = fmaxf(cbuf[d], 0.0f)       * fmaxf(cbuf[320 + j], 0.0f);
        float qe = fmaxf(cbuf[64 + d], 0.0f)  * fmaxf(cbuf[324 + j], 0.0f);
        float ge = sigf(cbuf[256 + d])        * sigf(cbuf[328 + j]);
        float kg = ke * ge;
        float dg = (1.0f - ge) * term;
        S = fmaf(dg, S, kg);
        float* sl = &sloc[tid * 13];
        #pragma unroll
        for (int r = 0; r < 8; ++r) {
            Kst[r] = fmaf(dg, Kst[r], kg * oc[r]);
            sl[r] = Kst[r] * qe;
        }
        sl[8] = S * qe;

        // --- V side (reads cbuf before bar2) ---
        if (tid < 64) {
            float bs = sigf(cbuf[192 + tid]);
            float vg = cbuf[128 + tid] * bs;
            float db = (1.0f - bs) * term;
            #pragma unroll
            for (int r = 0; r < 8; ++r)
                Vst[r] = fmaf(db, Vst[r], vg * oc[r]);
        }

        __syncthreads();   // bar2: sloc ready

        // --- partitioned reduction: warp w -> value w; warp 7 also v=8 ---
        {
            float x = 0.0f;
            #pragma unroll
            for (int i = 0; i < 8; ++i)
                x += sloc[(lane + 32 * i) * 13 + warp];
            x = warp_sum(x);
            if (lane == 0) kdqs[warp] = x;
            if (warp == 7) {
                float y = 0.0f;
                #pragma unroll
                for (int i = 0; i < 8; ++i)
                    y += sloc[(lane + 32 * i) * 13 + 8];
                y = warp_sum(y);
                if (lane == 0) kdqs[8] = y;
            }
        }
        __syncthreads();   // bar3: kdqs ready

        if (tid < 64) {
            float kv = 0.0f;
            #pragma unroll
            for (int r = 0; r < 8; ++r) kv = fmaf(Vst[r], kdqs[r], kv);
            float val = kv * 0.0625f * frcp_fast(kdqs[8] + 1e-6f);
            size_t idx = ((size_t)t * B_ + b) * D_MODEL + h * 64 + tid;
            split1(val, core_h + idx, core_l + idx);
        }
    }
    #undef SCAN_PREFETCH
}

// ---------------------------------------------------------------------------
// GRU stage 1 (vectorized, fast sigmoid)
// ---------------------------------------------------------------------------
__global__ __launch_bounds__(256)
void gru_pre(const float4* __restrict__ x, const float* __restrict__ Y3,
             const float* __restrict__ X2, uint2* __restrict__ rxh,
             uint2* __restrict__ rxl, float4* __restrict__ z, int n4)
{
    int i = blockIdx.x * 256 + threadIdx.x;
    if (i >= n4) return;
    int row = i >> 7, c = (i & 127) * 4;
    const float4 y0 = *(const float4*)&Y3[(size_t)row * 1536 + c];
    const float4 y1 = *(const float4*)&Y3[(size_t)row * 1536 + 512 + c];
    const float4 x0 = *(const float4*)&X2[(size_t)row * 1024 + c];
    const float4 x1 = *(const float4*)&X2[(size_t)row * 1024 + 512 + c];
    float4 xv = x[i];
    float4 zz;
    zz.x = sigf(y1.x + x1.x - 2.0f);
    zz.y = sigf(y1.y + x1.y - 2.0f);
    zz.z = sigf(y1.z + x1.z - 2.0f);
    zz.w = sigf(y1.w + x1.w - 2.0f);
    float4 rx;
    rx.x = sigf(y0.x + x0.x) * xv.x;
    rx.y = sigf(y0.y + x0.y) * xv.y;
    rx.z = sigf(y0.z + x0.z) * xv.z;
    rx.w = sigf(y0.w + x0.w) * xv.w;
    z[i] = zz;
    pack4(rx, rxh + i, rxl + i);
}

// ---------------------------------------------------------------------------
// Launch
// ---------------------------------------------------------------------------
template<typename Tp>
static Tp* symptr(const void* sym) {
    void* p = nullptr;
    cudaGetSymbolAddress(&p, sym);
    return (Tp*)p;
}

extern "C" void kernel_launch(void* const* d_in, const int* in_sizes, int n_in,
                              void* d_out, int out_size)
{
    const float* inputs   = (const float*)d_in[0];
    const int*   terms    = (const int*)  d_in[1];
    const float* tilde_k  = (const float*)d_in[2];
    const float* tilde_v  = (const float*)d_in[3];
    const float* s_prev   = (const float*)d_in[4];
    const float* tick     = (const float*)d_in[5];
    const float* w_proj   = (const float*)d_in[6];
    const float* b_proj   = (const float*)d_in[7];
    const float* w_attn   = (const float*)d_in[8];
    const float* b_attn   = (const float*)d_in[9];
    const float* ln1_g    = (const float*)d_in[10];
    const float* ln1_b    = (const float*)d_in[11];
    const float* ln2_g    = (const float*)d_in[12];
    const float* ln2_b    = (const float*)d_in[13];
    const float* gru1_w   = (const float*)d_in[14];
    const float* gru1_u   = (const float*)d_in[15];
    const float* gru2_w   = (const float*)d_in[16];
    const float* gru2_u   = (const float*)d_in[17];
    const float* ffc_w1   = (const float*)d_in[18];
    const float* ffc_b1   = (const float*)d_in[19];
    const float* ffc_w2   = (const float*)d_in[20];
    const float* ffc_b2   = (const float*)d_in[21];
    float* out = (float*)d_out;

    float* allproj = symptr<float>(g_allproj);
    float* Y3   = symptr<float>(g_Y3);
    float* X2   = symptr<float>(g_X2);
    float* zb   = symptr<float>(g_zb);
    float* gate1= symptr<float>(g_gate1);

    bf16 *in_h = symptr<bf16>(g_in_h),  *in_l = symptr<bf16>(g_in_l);
    bf16 *xn_h = symptr<bf16>(g_xn_h),  *xn_l = symptr<bf16>(g_xn_l);
    bf16 *co_h = symptr<bf16>(g_core_h),*co_l = symptr<bf16>(g_core_l);
    bf16 *ar_h = symptr<bf16>(g_arelu_h),*ar_l= symptr<bf16>(g_arelu_l);
    bf16 *rx_h = symptr<bf16>(g_rx_h),  *rx_l = symptr<bf16>(g_rx_l);
    bf16 *g1_h = symptr<bf16>(g_g1_h),  *g1_l = symptr<bf16>(g_g1_l);
    bf16 *ff_h = symptr<bf16>(g_ff_h),  *ff_l = symptr<bf16>(g_ff_l);
    bf16 *hd_h = symptr<bf16>(g_hid_h), *hd_l = symptr<bf16>(g_hid_l);

    bf16 *wp_h = symptr<bf16>(g_wproj_h), *wp_l = symptr<bf16>(g_wproj_l);
    bf16 *wa_h = symptr<bf16>(g_wattn_h), *wa_l = symptr<bf16>(g_wattn_l);
    bf16 *w1w_h= symptr<bf16>(g_g1w_h),   *w1w_l= symptr<bf16>(g_g1w_l);
    bf16 *w1u_h= symptr<bf16>(g_g1u_h),   *w1u_l= symptr<bf16>(g_g1u_l);
    bf16 *w2w_h= symptr<bf16>(g_g2w_h),   *w2w_l= symptr<bf16>(g_g2w_l);
    bf16 *w2u_h= symptr<bf16>(g_g2u_h),   *w2u_l= symptr<bf16>(g_g2u_l);
    bf16 *f1_h = symptr<bf16>(g_fw1_h),   *f1_l = symptr<bf16>(g_fw1_l);
    bf16 *f2_h = symptr<bf16>(g_fw2_h),   *f2_l = symptr<bf16>(g_fw2_l);

    cudaFuncSetAttribute(gemm_tc<0,0,128>, cudaFuncAttributeMaxDynamicSharedMemorySize, SMEM_G(128));
    cudaFuncSetAttribute(gemm_tc<1,1,128>, cudaFuncAttributeMaxDynamicSharedMemorySize, SMEM_G(128));
    cudaFuncSetAttribute(gemm_tc<0,2,128>, cudaFuncAttributeMaxDynamicSharedMemorySize, SMEM_G(128));
    cudaFuncSetAttribute(gemm_tc<0,0,256>, cudaFuncAttributeMaxDynamicSharedMemorySize, SMEM_G(256));
    cudaFuncSetAttribute(gemm_tc<1,1,256>, cudaFuncAttributeMaxDynamicSharedMemorySize, SMEM_G(256));

    const int n = NTOK * D_MODEL;
    const int n4 = n / 4;
    dim3 thr(256);
    const int eg4 = (n4 + 255) / 256;
    const int OFF2 = 2 * D_MODEL * D_MODEL;

    // 1) ln1 + raw input split
    ln_kernel<<<NTOK, thr>>>(inputs, ln1_g, ln1_b, xn_h, xn_l, in_h, in_l);

    // 2) mega weight split
    {
        SArgs sa;
        const float* srcs[8] = {w_proj, w_attn, gru1_w, gru1_u,
                                gru2_w, gru2_u, ffc_w1, ffc_w2};
        bf16* hs[8] = {wp_h, wa_h, w1w_h, w1u_h, w2w_h, w2u_h, f1_h, f2_h};
        bf16* ls[8] = {wp_l, wa_l, w1w_l, w1u_l, w2w_l, w2u_l, f1_l, f2_l};
        int cnts[8] = {WPROJ_N, WATTN_N, WGRU_N, WGRU_N,
                       WGRU_N, WGRU_N, WFFC1_N, WFFC2_N};
        int acc = 0;
        for (int k = 0; k < 8; ++k) {
            sa.s[k] = (const float4*)srcs[k];
            sa.h[k] = (uint2*)hs[k];
            sa.l[k] = (uint2*)ls[k];
            sa.off[k] = acc;
            acc += cnts[k] / 4;
        }
        sa.off[8] = acc;
        wsplit_all<<<(acc + 255) / 256, thr>>>(sa);
    }

    // 3) proj GEMM (NT=256)
    gemm_tc<0,0,256><<<dim3((TOTAL_PROJ + 255) / 256, 32), thr, SMEM_G(256)>>>(
        xn_h, xn_l, wp_h, wp_l, b_proj, allproj, nullptr, nullptr,
        nullptr, nullptr, nullptr, nullptr, nullptr, nullptr,
        NTOK, TOTAL_PROJ, D_MODEL);

    // 4) scan
    scan_kernel<<<B_ * H_, thr>>>(allproj, terms, tick, tilde_k, tilde_v,
                                  s_prev, co_h, co_l);

    // 5) attn (relu, hi/lo)
    gemm_tc<1,1,128><<<dim3(4, 32), thr, SMEM_G(128)>>>(
        co_h, co_l, wa_h, wa_l, b_attn, nullptr, ar_h, ar_l,
        nullptr, nullptr, nullptr, nullptr, nullptr, nullptr,
        NTOK, D_MODEL, D_MODEL);

    // 6) GRU1 Y3
    gemm_tc<0,0,256><<<dim3(6, 32), thr, SMEM_G(256)>>>(
        ar_h, ar_l, w1w_h, w1w_l, nullptr, Y3, nullptr, nullptr,
        nullptr, nullptr, nullptr, nullptr, nullptr, nullptr,
        NTOK, 3 * D_MODEL, D_MODEL);

    // 7) GRU1 X2
    gemm_tc<0,0,256><<<dim3(4, 32), thr, SMEM_G(256)>>>(
        in_h, in_l, w1u_h, w1u_l, nullptr, X2, nullptr, nullptr,
        nullptr, nullptr, nullptr, nullptr, nullptr, nullptr,
        NTOK, 2 * D_MODEL, D_MODEL);

    // 8) gru_pre 1
    gru_pre<<<eg4, thr>>>((const float4*)inputs, Y3, X2,
                          (uint2*)rx_h, (uint2*)rx_l, (float4*)zb, n4);

    // 9) RX GEMM + fused gru_post -> gate1 (+hi/lo)
    gemm_tc<0,2,128><<<dim3(4, 32), thr, SMEM_G(128)>>>(
        rx_h, rx_l, w1u_h + OFF2, w1u_l + OFF2, nullptr, nullptr, nullptr, nullptr,
        Y3, zb, inputs, gate1, g1_h, g1_l,
        NTOK, D_MODEL, D_MODEL);

    // 10) ln2
    ln_kernel<<<NTOK, thr>>>(gate1, ln2_g, ln2_b, xn_h, xn_l, nullptr, nullptr);

    // 11) FFC1 (relu, hi/lo)
    gemm_tc<1,1,256><<<dim3(8, 32), thr, SMEM_G(256)>>>(
        xn_h, xn_l, f1_h, f1_l, ffc_b1, nullptr, hd_h, hd_l,
        nullptr, nullptr, nullptr, nullptr, nullptr, nullptr,
        NTOK, D_FFC, D_MODEL);

    // 12) FFC2 (relu, hi/lo)
    gemm_tc<1,1,128><<<dim3(4, 32), thr, SMEM_G(128)>>>(
        hd_h, hd_l, f2_h, f2_l, ffc_b2, nullptr, ff_h, ff_l,
        nullptr, nullptr, nullptr, nullptr, nullptr, nullptr,
        NTOK, D_MODEL, D_FFC);

    // 13) GRU2 Y3
    gemm_tc<0,0,256><<<dim3(6, 32), thr, SMEM_G(256)>>>(
        ff_h, ff_l, w2w_h, w2w_l, nullptr, Y3, nullptr, nullptr,
        nullptr, nullptr, nullptr, nullptr, nullptr, nullptr,
        NTOK, 3 * D_MODEL, D_MODEL);

    // 14) GRU2 X2
    gemm_tc<0,0,256><<<dim3(4, 32), thr, SMEM_G(256)>>>(
        g1_h, g1_l, w2u_h, w2u_l, nullptr, X2, nullptr, nullptr,
        nullptr, nullptr, nullptr, nullptr, nullptr, nullptr,
        NTOK, 2 * D_MODEL, D_MODEL);

    // 15) gru_pre 2
    gru_pre<<<eg4, thr>>>((const float4*)gate1, Y3, X2,
                          (uint2*)rx_h, (uint2*)rx_l, (float4*)zb, n4);

    // 16) RX GEMM + fused gru_post -> out
    gemm_tc<0,2,128><<<dim3(4, 32), thr, SMEM_G(128)>>>(
        rx_h, rx_l, w2u_h + OFF2, w2u_l + OFF2, nullptr, nullptr, nullptr, nullptr,
        Y3, zb, gate1, out, nullptr, nullptr,
        NTOK, D_MODEL, D_MODEL);
}